// round 9
// baseline (speedup 1.0000x reference)
#include <cuda_runtime.h>
#include <cuda_bf16.h>
#include <math.h>

// ---------------- problem constants ----------------
#define NNODES 50000
#define NEDGES 600000
#define DIM    128
#define NET    4
#define NSTEPS 5
#define NGR    64

// ---------------- scratch (device globals; no allocation allowed) ----------------
__device__ __align__(128) float g_h[NNODES * DIM];
__device__ __align__(128) float g_gi[NNODES * 3 * DIM];
__device__ __align__(128) float g_gh[NNODES * 3 * DIM];
__device__ __align__(128) float g_z[NNODES * 2 * DIM];
__device__ __align__(128) float g_gat[NNODES * 2 * DIM];
__device__ float g_el[NNODES * 2];
__device__ float g_er[NNODES * 2];
__device__ int   g_deg[NNODES];
__device__ int   g_off[NNODES + 1];
__device__ int   g_cur[NNODES + 1];
__device__ int   g_csrc[NEDGES];
__device__ int   g_cety[NEDGES];
__device__ float g_hg[NGR * 2 * DIM];
__device__ float g_cls[2 * NGR * 64];
__device__ float g_cntf[NNODES * 4];

// bf16 hi/lo split buffers
__device__ __align__(128) __nv_bfloat16 g_a4h[NNODES * 512];   // per-etype aggregated h
__device__ __align__(128) __nv_bfloat16 g_a4l[NNODES * 512];
__device__ __align__(128) __nv_bfloat16 g_ah[NNODES * DIM];    // 'a' split
__device__ __align__(128) __nv_bfloat16 g_al[NNODES * DIM];
__device__ __align__(128) __nv_bfloat16 g_hbh[NNODES * DIM];   // h split
__device__ __align__(128) __nv_bfloat16 g_hbl[NNODES * DIM];
// split weights
__device__ __align__(128) __nv_bfloat16 g_bcath[DIM * 512], g_bcatl[DIM * 512];
__device__ __align__(128) __nv_bfloat16 g_wihh[384 * DIM],  g_wihl[384 * DIM];
__device__ __align__(128) __nv_bfloat16 g_whhh[384 * DIM],  g_whhl[384 * DIM];
__device__ __align__(128) __nv_bfloat16 g_wfch[256 * DIM],  g_wfcl[256 * DIM];

// =====================================================================
// bf16-split tensor-core GEMM with cp.async double buffering + ldmatrix
//   C[m,c] = sum_k A[m,k]*B[c,k]   (A = Ahi+Alo, B = Bhi+Blo, 3 passes)
// Block tile 128x128, 8 warps of 64x32, BK=32, runtime K (mult of 32).
// Epilogue mode0 (C!=null): fp32 out + optional bias[c].
// Epilogue mode1 (C==null): count-weighted b_et bias, split bf16 out.
// blockIdx.z==1 selects the second parameter set (fused twin GEMM).
// =====================================================================
#define LDK  40                    // padded bf16 row: 80B, conflict-free LDSM
#define TILE (128 * LDK)
#define GEMM_SMEM (2 * 2 * 2 * TILE * 2)   // 81920 bytes

__device__ __forceinline__ void mma16816(float* c, const unsigned* a, const unsigned* b) {
    asm volatile(
        "mma.sync.aligned.m16n8k16.row.col.f32.bf16.bf16.f32 "
        "{%0,%1,%2,%3},{%4,%5,%6,%7},{%8,%9},{%0,%1,%2,%3};"
        : "+f"(c[0]), "+f"(c[1]), "+f"(c[2]), "+f"(c[3])
        : "r"(a[0]), "r"(a[1]), "r"(a[2]), "r"(a[3]), "r"(b[0]), "r"(b[1]));
}
__device__ __forceinline__ void ldmx4(unsigned* r, unsigned addr) {
    asm volatile("ldmatrix.sync.aligned.m8n8.x4.shared.b16 {%0,%1,%2,%3}, [%4];"
                 : "=r"(r[0]), "=r"(r[1]), "=r"(r[2]), "=r"(r[3]) : "r"(addr));
}
__device__ __forceinline__ void ldmx2(unsigned* r, unsigned addr) {
    asm volatile("ldmatrix.sync.aligned.m8n8.x2.shared.b16 {%0,%1}, [%2];"
                 : "=r"(r[0]), "=r"(r[1]) : "r"(addr));
}
__device__ __forceinline__ void cpasync16(unsigned dst, const void* src, int srcsize) {
    asm volatile("cp.async.cg.shared.global [%0], [%1], 16, %2;"
                 :: "r"(dst), "l"(src), "r"(srcsize));
}

__global__ __launch_bounds__(256, 2) void bgemm3(
    const __nv_bfloat16* __restrict__ Ahi, const __nv_bfloat16* __restrict__ Alo,
    const __nv_bfloat16* __restrict__ Bhi, const __nv_bfloat16* __restrict__ Blo,
    const __nv_bfloat16* __restrict__ A2hi, const __nv_bfloat16* __restrict__ A2lo,
    const __nv_bfloat16* __restrict__ B2hi, const __nv_bfloat16* __restrict__ B2lo,
    int M, int Ncols, int K,
    const float* __restrict__ bias, const float* __restrict__ bias2,
    const float* __restrict__ cnt, const float* __restrict__ bet,
    float* __restrict__ C, float* __restrict__ C2,
    __nv_bfloat16* __restrict__ Chi, __nv_bfloat16* __restrict__ Clo)
{
    extern __shared__ __nv_bfloat16 smem[];
    if (blockIdx.z == 1) {
        Ahi = A2hi; Alo = A2lo; Bhi = B2hi; Blo = B2lo; bias = bias2; C = C2;
    }
    const int tid = threadIdx.x;
    const int rowBase = blockIdx.y * 128, colBase = blockIdx.x * 128;
    const unsigned sbase = (unsigned)__cvta_generic_to_shared(smem);

    auto stage = [&](int buf, int kk) {
#pragma unroll
        for (int i = 0; i < 8; i++) {
            int flat = i * 256 + tid;
            int chunk = flat & 3;
            int row = (flat >> 2) & 127;
            int hl = (flat >> 9) & 1;
            int ab = flat >> 10;
            unsigned dst = sbase + (unsigned)(((buf * 2 + ab) * 2 + hl) * TILE
                                              + row * LDK + chunk * 8) * 2u;
            const __nv_bfloat16* src;
            int ok;
            if (ab == 0) {
                int gr = rowBase + row; ok = (gr < M); if (!ok) gr = 0;
                src = (hl ? Alo : Ahi) + (size_t)gr * K + kk + chunk * 8;
            } else {
                int gc = colBase + row; ok = (gc < Ncols); if (!ok) gc = 0;
                src = (hl ? Blo : Bhi) + (size_t)gc * K + kk + chunk * 8;
            }
            cpasync16(dst, src, ok ? 16 : 0);
        }
        asm volatile("cp.async.commit_group;");
    };

    const int lane = tid & 31, warp = tid >> 5;
    const int warpRow = (warp >> 2) * 64, warpCol = (warp & 3) * 32;
    const unsigned aoff = (unsigned)(((warpRow + (lane & 15)) * LDK + (lane >> 4) * 8) * 2);
    const unsigned boff = (unsigned)(((warpCol + (lane & 7)) * LDK + ((lane >> 3) & 1) * 8) * 2);

    float acc[4][4][4];
#pragma unroll
    for (int i = 0; i < 4; i++)
#pragma unroll
        for (int j = 0; j < 4; j++)
#pragma unroll
            for (int q = 0; q < 4; q++) acc[i][j][q] = 0.f;

    stage(0, 0);
    const int nk = K >> 5;
    for (int it = 0; it < nk; it++) {
        int buf = it & 1;
        if (it + 1 < nk) {
            stage(buf ^ 1, (it + 1) * 32);
            asm volatile("cp.async.wait_group 1;");
        } else {
            asm volatile("cp.async.wait_group 0;");
        }
        __syncthreads();
        unsigned aHi = sbase + (unsigned)((buf * 4 + 0) * TILE) * 2u;
        unsigned aLo = sbase + (unsigned)((buf * 4 + 1) * TILE) * 2u;
        unsigned bHi = sbase + (unsigned)((buf * 4 + 2) * TILE) * 2u;
        unsigned bLo = sbase + (unsigned)((buf * 4 + 3) * TILE) * 2u;
#pragma unroll
        for (int ks = 0; ks < 2; ks++) {
            unsigned kb = ks * 32;      // 16 bf16 = 32B
            unsigned af[4][4], bh[4][2], bl[4][2];
#pragma unroll
            for (int i = 0; i < 4; i++) ldmx4(af[i], aHi + aoff + kb + i * 16 * LDK * 2);
#pragma unroll
            for (int j = 0; j < 4; j++) ldmx2(bh[j], bHi + boff + kb + j * 8 * LDK * 2);
#pragma unroll
            for (int j = 0; j < 4; j++) ldmx2(bl[j], bLo + boff + kb + j * 8 * LDK * 2);
#pragma unroll
            for (int i = 0; i < 4; i++)
#pragma unroll
                for (int j = 0; j < 4; j++) mma16816(acc[i][j], af[i], bh[j]);  // hi*hi
#pragma unroll
            for (int i = 0; i < 4; i++)
#pragma unroll
                for (int j = 0; j < 4; j++) mma16816(acc[i][j], af[i], bl[j]);  // hi*lo
#pragma unroll
            for (int i = 0; i < 4; i++) ldmx4(af[i], aLo + aoff + kb + i * 16 * LDK * 2);
#pragma unroll
            for (int i = 0; i < 4; i++)
#pragma unroll
                for (int j = 0; j < 4; j++) mma16816(acc[i][j], af[i], bh[j]);  // lo*hi
        }
        __syncthreads();
    }

    // ---- epilogue ----
    const int rr = lane >> 2, cc = (lane & 3) * 2;
    if (C) {
#pragma unroll
        for (int i = 0; i < 4; i++) {
            int gr0 = rowBase + warpRow + i * 16 + rr;
#pragma unroll
            for (int j = 0; j < 4; j++) {
                int gc = colBase + warpCol + j * 8 + cc;
                float b0 = bias ? bias[gc] : 0.f;
                float b1 = bias ? bias[gc + 1] : 0.f;
                if (gr0 < M) {
                    C[(size_t)gr0 * Ncols + gc]     = acc[i][j][0] + b0;
                    C[(size_t)gr0 * Ncols + gc + 1] = acc[i][j][1] + b1;
                }
                if (gr0 + 8 < M) {
                    C[(size_t)(gr0 + 8) * Ncols + gc]     = acc[i][j][2] + b0;
                    C[(size_t)(gr0 + 8) * Ncols + gc + 1] = acc[i][j][3] + b1;
                }
            }
        }
    } else {
#pragma unroll
        for (int i = 0; i < 4; i++) {
            int gr0 = rowBase + warpRow + i * 16 + rr;
            float4 c0 = make_float4(0, 0, 0, 0), c8 = make_float4(0, 0, 0, 0);
            if (gr0 < M)     c0 = *reinterpret_cast<const float4*>(cnt + (size_t)gr0 * 4);
            if (gr0 + 8 < M) c8 = *reinterpret_cast<const float4*>(cnt + (size_t)(gr0 + 8) * 4);
#pragma unroll
            for (int j = 0; j < 4; j++) {
                int gc = colBase + warpCol + j * 8 + cc;
                float be0[2], be1[2];
#pragma unroll
                for (int q = 0; q < 2; q++) {
                    be0[q] = c0.x * bet[gc + q] + c0.y * bet[128 + gc + q]
                           + c0.z * bet[256 + gc + q] + c0.w * bet[384 + gc + q];
                    be1[q] = c8.x * bet[gc + q] + c8.y * bet[128 + gc + q]
                           + c8.z * bet[256 + gc + q] + c8.w * bet[384 + gc + q];
                }
                if (gr0 < M) {
                    float v0 = acc[i][j][0] + be0[0], v1 = acc[i][j][1] + be0[1];
                    __nv_bfloat16 h0 = __float2bfloat16(v0), h1 = __float2bfloat16(v1);
                    __nv_bfloat162 hp; hp.x = h0; hp.y = h1;
                    __nv_bfloat162 lp;
                    lp.x = __float2bfloat16(v0 - __bfloat162float(h0));
                    lp.y = __float2bfloat16(v1 - __bfloat162float(h1));
                    *reinterpret_cast<__nv_bfloat162*>(&Chi[(size_t)gr0 * Ncols + gc]) = hp;
                    *reinterpret_cast<__nv_bfloat162*>(&Clo[(size_t)gr0 * Ncols + gc]) = lp;
                }
                if (gr0 + 8 < M) {
                    float v0 = acc[i][j][2] + be1[0], v1 = acc[i][j][3] + be1[1];
                    __nv_bfloat16 h0 = __float2bfloat16(v0), h1 = __float2bfloat16(v1);
                    __nv_bfloat162 hp; hp.x = h0; hp.y = h1;
                    __nv_bfloat162 lp;
                    lp.x = __float2bfloat16(v0 - __bfloat162float(h0));
                    lp.y = __float2bfloat16(v1 - __bfloat162float(h1));
                    *reinterpret_cast<__nv_bfloat162*>(&Chi[(size_t)(gr0 + 8) * Ncols + gc]) = hp;
                    *reinterpret_cast<__nv_bfloat162*>(&Clo[(size_t)(gr0 + 8) * Ncols + gc]) = lp;
                }
            }
        }
    }
}

// ---------------- split helpers ----------------
__global__ void split_kernel(const float* __restrict__ s, __nv_bfloat16* __restrict__ hi,
                             __nv_bfloat16* __restrict__ lo, int n) {
    int i = blockIdx.x * blockDim.x + threadIdx.x;
    if (i < n) {
        float v = s[i];
        __nv_bfloat16 h = __float2bfloat16(v);
        hi[i] = h;
        lo[i] = __float2bfloat16(v - __bfloat162float(h));
    }
}

// Bcat[d][k*128+e] = W_et[k][d][e]  (rows d, K=512)
__global__ void bcat_kernel(const float* __restrict__ wet, __nv_bfloat16* __restrict__ hi,
                            __nv_bfloat16* __restrict__ lo) {
    int i = blockIdx.x * blockDim.x + threadIdx.x;
    if (i < 128 * 512) {
        int d = i >> 9, col = i & 511, k = col >> 7, e = col & 127;
        float v = wet[(k << 14) + (d << 7) + e];
        __nv_bfloat16 h = __float2bfloat16(v);
        hi[i] = h;
        lo[i] = __float2bfloat16(v - __bfloat162float(h));
    }
}

// ---------------- CSR construction ----------------
__global__ void zero_int_kernel(int* p, int n) {
    int i = blockIdx.x * blockDim.x + threadIdx.x;
    if (i < n) p[i] = 0;
}
__global__ void hist_kernel(const int* __restrict__ dst, int* deg, int E) {
    int i = blockIdx.x * blockDim.x + threadIdx.x;
    if (i < E) atomicAdd(&deg[dst[i]], 1);
}
__global__ void scan_kernel(const int* __restrict__ deg, int* off, int* cur, int n) {
    __shared__ int tmp[1024];
    __shared__ int carry_s;
    int t = threadIdx.x;
    if (t == 0) { off[0] = 0; cur[0] = 0; carry_s = 0; }
    __syncthreads();
    for (int base = 0; base < n; base += 1024) {
        int v = (base + t < n) ? deg[base + t] : 0;
        tmp[t] = v;
        __syncthreads();
        for (int s = 1; s < 1024; s <<= 1) {
            int x = (t >= s) ? tmp[t - s] : 0;
            __syncthreads();
            tmp[t] += x;
            __syncthreads();
        }
        int incl = tmp[t] + carry_s;
        if (base + t < n) { off[base + t + 1] = incl; cur[base + t + 1] = incl; }
        __syncthreads();
        if (t == 1023) carry_s = incl;
        __syncthreads();
    }
}
__global__ void scatter_kernel(const int* __restrict__ src, const int* __restrict__ dst,
                               const int* __restrict__ et, int* cur,
                               int* csrc, int* cety, int E) {
    int i = blockIdx.x * blockDim.x + threadIdx.x;
    if (i >= E) return;
    int d = dst[i];
    int p = atomicAdd(&cur[d], 1);
    csrc[p] = src[i];
    cety[p] = et[i];
}

// ---------------- per-etype aggregation of h over dst + counts ----------------
__global__ void agg4_kernel(const int* __restrict__ off, const int* __restrict__ csrc,
                            const int* __restrict__ cety, const float* __restrict__ h,
                            __nv_bfloat16* __restrict__ a4h, __nv_bfloat16* __restrict__ a4l,
                            float* __restrict__ cntf) {
    int n = blockIdx.x, tid = threadIdx.x;   // 128 threads = feature dim
    int s0 = off[n], s1 = off[n + 1];
    __shared__ int sbuf[128], kbuf[128];
    float a0 = 0.f, a1 = 0.f, a2 = 0.f, a3 = 0.f;
    int c0 = 0, c1 = 0, c2 = 0, c3 = 0;
    for (int base = s0; base < s1; base += 128) {
        int cnt = min(128, s1 - base);
        if (tid < cnt) { sbuf[tid] = csrc[base + tid]; kbuf[tid] = cety[base + tid]; }
        __syncthreads();
        for (int i = 0; i < cnt; i++) {
            float v = __ldg(&h[(size_t)sbuf[i] * DIM + tid]);
            int k = kbuf[i];
            if (k == 0)      { a0 += v; c0++; }
            else if (k == 1) { a1 += v; c1++; }
            else if (k == 2) { a2 += v; c2++; }
            else             { a3 += v; c3++; }
        }
        __syncthreads();
    }
    size_t b = (size_t)n * 512 + tid;
    float av[4] = {a0, a1, a2, a3};
#pragma unroll
    for (int k = 0; k < 4; k++) {
        float v = av[k];
        __nv_bfloat16 hh = __float2bfloat16(v);
        a4h[b + k * 128] = hh;
        a4l[b + k * 128] = __float2bfloat16(v - __bfloat162float(hh));
    }
    if (tid < 4) {
        int cv = (tid == 0) ? c0 : (tid == 1) ? c1 : (tid == 2) ? c2 : c3;
        cntf[n * 4 + tid] = (float)cv;
    }
}

// ---------------- GRU elementwise (+ h split output) ----------------
__global__ void gru_kernel(const float* __restrict__ gi, const float* __restrict__ gh,
                           const float* __restrict__ hold, float* __restrict__ hnew,
                           __nv_bfloat16* __restrict__ hbh, __nv_bfloat16* __restrict__ hbl,
                           int n) {
    int idx = blockIdx.x * blockDim.x + threadIdx.x;
    if (idx >= n * DIM) return;
    int node = idx >> 7, d = idx & 127;
    const float* gip = gi + (size_t)node * 384;
    const float* ghp = gh + (size_t)node * 384;
    float r  = 1.f / (1.f + expf(-(gip[d] + ghp[d])));
    float zq = 1.f / (1.f + expf(-(gip[128 + d] + ghp[128 + d])));
    float nn = tanhf(gip[256 + d] + r * ghp[256 + d]);
    float h0 = hold[idx];
    float hv = (1.f - zq) * nn + zq * h0;
    hnew[idx] = hv;
    __nv_bfloat16 hh = __float2bfloat16(hv);
    hbh[idx] = hh;
    hbl[idx] = __float2bfloat16(hv - __bfloat162float(hh));
}

// ---------------- L2 normalize + sigmoid -> split bf16 ----------------
__global__ void normsig_kernel(const float* __restrict__ h,
                               __nv_bfloat16* __restrict__ hbh, __nv_bfloat16* __restrict__ hbl) {
    int n = blockIdx.x, tid = threadIdx.x;  // 128
    __shared__ float red[128];
    float v = h[(size_t)n * DIM + tid];
    red[tid] = v * v;
    __syncthreads();
    for (int s = 64; s; s >>= 1) {
        if (tid < s) red[tid] += red[tid + s];
        __syncthreads();
    }
    float norm = fmaxf(sqrtf(red[0]), 1e-12f);
    float x = 1.f / (1.f + expf(-(v / norm)));
    __nv_bfloat16 hh = __float2bfloat16(x);
    hbh[(size_t)n * DIM + tid] = hh;
    hbl[(size_t)n * DIM + tid] = __float2bfloat16(x - __bfloat162float(hh));
}

// ---------------- GAT: el/er per node ----------------
__global__ void eler_kernel(const float* __restrict__ z, const float* __restrict__ al,
                            const float* __restrict__ ar, float* __restrict__ el,
                            float* __restrict__ er) {
    int n = blockIdx.x, tid = threadIdx.x;  // 256 = (head, d)
    __shared__ float sl[256], sr[256];
    float zv = z[(size_t)n * 256 + tid];
    sl[tid] = zv * al[tid];
    sr[tid] = zv * ar[tid];
    __syncthreads();
    int lane = tid & 127;
    for (int s = 64; s; s >>= 1) {
        if (lane < s) { sl[tid] += sl[tid + s]; sr[tid] += sr[tid + s]; }
        __syncthreads();
    }
    if (lane == 0) {
        int h = tid >> 7;
        el[n * 2 + h] = sl[tid];
        er[n * 2 + h] = sr[tid];
    }
}

// ---------------- GAT: edge softmax + weighted aggregation ----------------
__global__ void gat_kernel(const int* __restrict__ off, const int* __restrict__ csrc,
                           const float* __restrict__ el, const float* __restrict__ er,
                           const float* __restrict__ z, const float* __restrict__ bias,
                           float* __restrict__ outp) {
    int n = blockIdx.x, tid = threadIdx.x;  // 256 = (head, d)
    int h = tid >> 7, lane = tid & 127;
    int s0 = off[n], s1 = off[n + 1];
    float er_nh = er[n * 2 + h];

    __shared__ float red[256];
    __shared__ float mden[4];
    __shared__ float wbuf[2][128];
    __shared__ int   sbuf[128];

    float lmax = -3.0e38f;
    for (int e = s0 + lane; e < s1; e += 128) {
        float x = el[csrc[e] * 2 + h] + er_nh;
        x = x > 0.f ? x : 0.2f * x;
        lmax = fmaxf(lmax, x);
    }
    red[tid] = lmax;
    __syncthreads();
    for (int s = 64; s; s >>= 1) {
        if (lane < s) red[tid] = fmaxf(red[tid], red[tid + s]);
        __syncthreads();
    }
    if (lane == 0) mden[h] = red[tid];
    __syncthreads();
    float m = mden[h];

    float lsum = 0.f;
    for (int e = s0 + lane; e < s1; e += 128) {
        float x = el[csrc[e] * 2 + h] + er_nh;
        x = x > 0.f ? x : 0.2f * x;
        lsum += expf(x - m);
    }
    red[tid] = lsum;
    __syncthreads();
    for (int s = 64; s; s >>= 1) {
        if (lane < s) red[tid] += red[tid + s];
        __syncthreads();
    }
    if (lane == 0) mden[2 + h] = 1.f / red[tid];
    __syncthreads();
    float invden = mden[2 + h];

    float acc = 0.f;
    for (int base = s0; base < s1; base += 128) {
        int cnt = min(128, s1 - base);
        if (lane < cnt) {
            int sn = csrc[base + lane];
            float x = el[sn * 2 + h] + er_nh;
            x = x > 0.f ? x : 0.2f * x;
            wbuf[h][lane] = expf(x - m) * invden;
            if (h == 0) sbuf[lane] = sn;
        }
        __syncthreads();
        for (int i = 0; i < cnt; i++)
            acc = fmaf(wbuf[h][i], z[(size_t)sbuf[i] * 256 + tid], acc);
        __syncthreads();
    }
    float o = acc + bias[tid];
    outp[(size_t)n * 256 + tid] = fmaxf(o, 0.f);
}

// ---------------- graph mean-pool ----------------
__global__ void pool_kernel(const int* __restrict__ gid, const float* __restrict__ hgat,
                            float* __restrict__ hg, int n) {
    int b = blockIdx.x, tid = threadIdx.x;  // 256
    __shared__ int s_lo, s_hi;
    if (tid == 0) {
        int lo = 0, hi = n;
        while (lo < hi) { int mid = (lo + hi) >> 1; if (gid[mid] < b) lo = mid + 1; else hi = mid; }
        s_lo = lo;
        lo = 0; hi = n;
        while (lo < hi) { int mid = (lo + hi) >> 1; if (gid[mid] < b + 1) lo = mid + 1; else hi = mid; }
        s_hi = lo;
    }
    __syncthreads();
    float acc = 0.f;
    for (int node = s_lo; node < s_hi; node++)
        acc += hgat[(size_t)node * 256 + tid];
    float cnt = (float)(s_hi - s_lo);
    hg[b * 256 + tid] = acc / fmaxf(cnt, 1.f);
}

// ---------------- classifier ----------------
__global__ void cls_kernel(const float* __restrict__ hg, const float* __restrict__ Wc,
                           const float* __restrict__ bc, float* __restrict__ outc) {
    int b = blockIdx.x, tid = threadIdx.x;  // 64 = (head, c)
    __shared__ float sh[256];
    for (int i = tid; i < 256; i += 64) sh[i] = hg[b * 256 + i];
    __syncthreads();
    int h = tid >> 5, c = tid & 31;
    float s = bc[c];
    for (int d = 0; d < DIM; d++)
        s = fmaf(sh[h * 128 + d], Wc[c * 128 + d], s);
    outc[b * 64 + tid] = s;
}

// ---------------- pairwise distance + softmax over heads ----------------
__global__ void final_kernel(const float* __restrict__ c1, const float* __restrict__ c2,
                             float* __restrict__ out) {
    int b = threadIdx.x;
    if (b >= NGR) return;
    float dist[2];
    for (int h = 0; h < 2; h++) {
        float ss = 0.f;
        for (int c = 0; c < 32; c++) {
            float diff = c1[b * 64 + h * 32 + c] - c2[b * 64 + h * 32 + c] + 1e-6f;
            ss += diff * diff;
        }
        dist[h] = sqrtf(ss);
    }
    float mx = fmaxf(dist[0], dist[1]);
    float e0 = expf(dist[0] - mx), e1 = expf(dist[1] - mx);
    float inv = 1.f / (e0 + e1);
    out[b * 2 + 0] = e0 * inv;
    out[b * 2 + 1] = e1 * inv;
}

// ---------------- host launcher ----------------
extern "C" void kernel_launch(void* const* d_in, const int* in_sizes, int n_in,
                              void* d_out, int out_size) {
    const float* feat[2] = {(const float*)d_in[0], (const float*)d_in[1]};
    const int* srcs[2] = {(const int*)d_in[2], (const int*)d_in[6]};
    const int* dsts[2] = {(const int*)d_in[3], (const int*)d_in[7]};
    const int* ets[2]  = {(const int*)d_in[4], (const int*)d_in[8]};
    const int* gids[2] = {(const int*)d_in[5], (const int*)d_in[9]};
    const float* W_et   = (const float*)d_in[10];
    const float* b_et   = (const float*)d_in[11];
    const float* W_ih   = (const float*)d_in[12];
    const float* W_hh   = (const float*)d_in[13];
    const float* b_ih   = (const float*)d_in[14];
    const float* b_hh   = (const float*)d_in[15];
    const float* W_fc   = (const float*)d_in[16];
    const float* attn_l = (const float*)d_in[17];
    const float* attn_r = (const float*)d_in[18];
    const float* g_bias = (const float*)d_in[19];
    const float* W_cls  = (const float*)d_in[20];
    const float* b_cls  = (const float*)d_in[21];

    int N = in_sizes[0] / DIM;
    int E = in_sizes[2];

    float *h, *gi, *gh, *z, *gat, *el, *er, *hg, *cls, *cntf;
    int *deg, *off, *cur, *csrc, *cety;
    __nv_bfloat16 *a4h, *a4l, *ah, *al, *hbh, *hbl;
    __nv_bfloat16 *bcath, *bcatl, *wihh, *wihl, *whhh, *whhl, *wfch, *wfcl;
    cudaGetSymbolAddress((void**)&h, g_h);
    cudaGetSymbolAddress((void**)&gi, g_gi);
    cudaGetSymbolAddress((void**)&gh, g_gh);
    cudaGetSymbolAddress((void**)&z, g_z);
    cudaGetSymbolAddress((void**)&gat, g_gat);
    cudaGetSymbolAddress((void**)&el, g_el);
    cudaGetSymbolAddress((void**)&er, g_er);
    cudaGetSymbolAddress((void**)&deg, g_deg);
    cudaGetSymbolAddress((void**)&off, g_off);
    cudaGetSymbolAddress((void**)&cur, g_cur);
    cudaGetSymbolAddress((void**)&csrc, g_csrc);
    cudaGetSymbolAddress((void**)&cety, g_cety);
    cudaGetSymbolAddress((void**)&hg, g_hg);
    cudaGetSymbolAddress((void**)&cls, g_cls);
    cudaGetSymbolAddress((void**)&cntf, g_cntf);
    cudaGetSymbolAddress((void**)&a4h, g_a4h);
    cudaGetSymbolAddress((void**)&a4l, g_a4l);
    cudaGetSymbolAddress((void**)&ah, g_ah);
    cudaGetSymbolAddress((void**)&al, g_al);
    cudaGetSymbolAddress((void**)&hbh, g_hbh);
    cudaGetSymbolAddress((void**)&hbl, g_hbl);
    cudaGetSymbolAddress((void**)&bcath, g_bcath);
    cudaGetSymbolAddress((void**)&bcatl, g_bcatl);
    cudaGetSymbolAddress((void**)&wihh, g_wihh);
    cudaGetSymbolAddress((void**)&wihl, g_wihl);
    cudaGetSymbolAddress((void**)&whhh, g_whhh);
    cudaGetSymbolAddress((void**)&whhl, g_whhl);
    cudaGetSymbolAddress((void**)&wfch, g_wfch);
    cudaGetSymbolAddress((void**)&wfcl, g_wfcl);

    cudaFuncSetAttribute(bgemm3, cudaFuncAttributeMaxDynamicSharedMemorySize, GEMM_SMEM);

    // split weights (once per launch; tiny)
    bcat_kernel<<<(128 * 512 + 255) / 256, 256>>>(W_et, bcath, bcatl);
    split_kernel<<<(384 * 128 + 255) / 256, 256>>>(W_ih, wihh, wihl, 384 * 128);
    split_kernel<<<(384 * 128 + 255) / 256, 256>>>(W_hh, whhh, whhl, 384 * 128);
    split_kernel<<<(256 * 128 + 255) / 256, 256>>>(W_fc, wfch, wfcl, 256 * 128);

    int mblocks = (N + 127) / 128;

    for (int g = 0; g < 2; g++) {
        // CSR by dst
        zero_int_kernel<<<(N + 255) / 256, 256>>>(deg, N);
        hist_kernel<<<(E + 255) / 256, 256>>>(dsts[g], deg, E);
        scan_kernel<<<1, 1024>>>(deg, off, cur, N);
        scatter_kernel<<<(E + 255) / 256, 256>>>(srcs[g], dsts[g], ets[g], cur, csrc, cety, E);

        // split initial features for GEMM consumption
        split_kernel<<<(N * DIM + 255) / 256, 256>>>(feat[g], hbh, hbl, N * DIM);

        const float* hcur = feat[g];
        for (int s = 0; s < NSTEPS; s++) {
            // per-etype aggregation of h -> A4 split + counts
            agg4_kernel<<<N, DIM>>>(off, csrc, cety, hcur, a4h, a4l, cntf);
            // a = A4 @ Bcat^T + cnt-weighted b_et   (K=512, split bf16 out)
            bgemm3<<<dim3(1, mblocks, 1), 256, GEMM_SMEM>>>(
                a4h, a4l, bcath, bcatl, nullptr, nullptr, nullptr, nullptr,
                N, 128, 512, nullptr, nullptr, cntf, b_et,
                nullptr, nullptr, ah, al);
            // fused: gi = a @ W_ih^T + b_ih ; gh = h @ W_hh^T + b_hh
            bgemm3<<<dim3(3, mblocks, 2), 256, GEMM_SMEM>>>(
                ah, al, wihh, wihl, hbh, hbl, whhh, whhl,
                N, 384, 128, b_ih, b_hh, nullptr, nullptr,
                gi, gh, nullptr, nullptr);
            gru_kernel<<<(N * DIM + 255) / 256, 256>>>(gi, gh, hcur, h, hbh, hbl, N);
            hcur = h;
        }

        normsig_kernel<<<N, DIM>>>(h, hbh, hbl);

        // GAT: z = h @ W_fc^T
        bgemm3<<<dim3(2, mblocks, 1), 256, GEMM_SMEM>>>(
            hbh, hbl, wfch, wfcl, nullptr, nullptr, nullptr, nullptr,
            N, 256, 128, nullptr, nullptr, nullptr, nullptr,
            z, nullptr, nullptr, nullptr);
        eler_kernel<<<N, 256>>>(z, attn_l, attn_r, el, er);
        gat_kernel<<<N, 256>>>(off, csrc, el, er, z, g_bias, gat);

        // pool + classify
        pool_kernel<<<NGR, 256>>>(gids[g], gat, hg, N);
        cls_kernel<<<NGR, 64>>>(hg, W_cls, b_cls, cls + g * NGR * 64);
    }

    final_kernel<<<1, 64>>>(cls, cls + NGR * 64, (float*)d_out);
}

// round 10
// speedup vs baseline: 1.4558x; 1.4558x over previous
#include <cuda_runtime.h>
#include <cuda_bf16.h>
#include <math.h>

// ---------------- problem constants ----------------
#define NNODES 50000
#define NEDGES 600000
#define DIM    128
#define NET    4
#define NSTEPS 5
#define NGR    64

// ---------------- scratch (device globals; no allocation allowed) ----------------
__device__ __align__(128) float g_t[NET * NNODES * DIM];   // per-etype transformed feats (fp32)
__device__ __align__(128) float g_h[NNODES * DIM];
__device__ __align__(128) float g_gi[NNODES * 3 * DIM];
__device__ __align__(128) float g_gh[NNODES * 3 * DIM];
__device__ __align__(128) float g_z[NNODES * 2 * DIM];
__device__ __align__(128) float g_gat[NNODES * 2 * DIM];
__device__ float g_el[NNODES * 2];
__device__ float g_er[NNODES * 2];
__device__ int   g_deg[NNODES];
__device__ int   g_off[NNODES + 1];
__device__ int   g_cur[NNODES + 1];
__device__ int   g_cgidx[NEDGES];                // etype*N + src, dst-sorted
__device__ int   g_csrc[NEDGES];                 // src, dst-sorted
__device__ float g_hg[NGR * 2 * DIM];
__device__ float g_cls[2 * NGR * 64];

// bf16 hi/lo split activation buffers
__device__ __align__(128) __nv_bfloat16 g_ah[NNODES * DIM];    // 'a' split
__device__ __align__(128) __nv_bfloat16 g_al[NNODES * DIM];
__device__ __align__(128) __nv_bfloat16 g_hbh[NNODES * DIM];   // h split
__device__ __align__(128) __nv_bfloat16 g_hbl[NNODES * DIM];
// split weights
__device__ __align__(128) __nv_bfloat16 g_weth[NET * DIM * DIM], g_wetl[NET * DIM * DIM];
__device__ __align__(128) __nv_bfloat16 g_wihh[384 * DIM],  g_wihl[384 * DIM];
__device__ __align__(128) __nv_bfloat16 g_whhh[384 * DIM],  g_whhl[384 * DIM];
__device__ __align__(128) __nv_bfloat16 g_wfch[256 * DIM],  g_wfcl[256 * DIM];

// =====================================================================
// bf16-split tensor-core GEMM (pre-split operands, cp.async + ldmatrix)
//   C[m,c] = sum_k A[m,k]*B[c,k] + bias[c]     (K = 128 fixed)
// A = Ahi+Alo [M,128], B = Bhi+Blo [Ncols,128]; 3 MMA passes (hh, hl, lh).
// Block tile 128x128, 8 warps of 64x32, BK=32, single-buffered 40KB smem.
// blockIdx.z batches B/C/bias (used for the 4 etype weights).
// =====================================================================
#define LDK  40                    // padded bf16 row: 80B, conflict-free LDSM
#define TILE (128 * LDK)

__device__ __forceinline__ void mma16816(float* c, const unsigned* a, const unsigned* b) {
    asm volatile(
        "mma.sync.aligned.m16n8k16.row.col.f32.bf16.bf16.f32 "
        "{%0,%1,%2,%3},{%4,%5,%6,%7},{%8,%9},{%0,%1,%2,%3};"
        : "+f"(c[0]), "+f"(c[1]), "+f"(c[2]), "+f"(c[3])
        : "r"(a[0]), "r"(a[1]), "r"(a[2]), "r"(a[3]), "r"(b[0]), "r"(b[1]));
}
__device__ __forceinline__ void ldmx4(unsigned* r, unsigned addr) {
    asm volatile("ldmatrix.sync.aligned.m8n8.x4.shared.b16 {%0,%1,%2,%3}, [%4];"
                 : "=r"(r[0]), "=r"(r[1]), "=r"(r[2]), "=r"(r[3]) : "r"(addr));
}
__device__ __forceinline__ void ldmx2(unsigned* r, unsigned addr) {
    asm volatile("ldmatrix.sync.aligned.m8n8.x2.shared.b16 {%0,%1}, [%2];"
                 : "=r"(r[0]), "=r"(r[1]) : "r"(addr));
}
__device__ __forceinline__ void cpasync16(unsigned dst, const void* src, int srcsize) {
    asm volatile("cp.async.cg.shared.global [%0], [%1], 16, %2;"
                 :: "r"(dst), "l"(src), "r"(srcsize));
}

__global__ __launch_bounds__(256) void bgemm(
    const __nv_bfloat16* __restrict__ Ahi, const __nv_bfloat16* __restrict__ Alo,
    const __nv_bfloat16* __restrict__ Bhi, const __nv_bfloat16* __restrict__ Blo,
    const float* __restrict__ bias, float* __restrict__ C,
    int M, int Ncols, int strideB, int strideC, int strideBias)
{
    __shared__ __align__(16) __nv_bfloat16 S[4][128][LDK];   // Ahi, Alo, Bhi, Blo

    const int bz = blockIdx.z;
    Bhi += (size_t)bz * strideB;
    Blo += (size_t)bz * strideB;
    C   += (size_t)bz * strideC;
    const float* bp = bias ? (bias + (size_t)bz * strideBias) : nullptr;

    const int tid = threadIdx.x;
    const int rowBase = blockIdx.y * 128, colBase = blockIdx.x * 128;
    const unsigned sbase = (unsigned)__cvta_generic_to_shared(&S[0][0][0]);

    const int lane = tid & 31, warp = tid >> 5;
    const int warpRow = (warp >> 2) * 64, warpCol = (warp & 3) * 32;
    const unsigned aoff = (unsigned)(((warpRow + (lane & 15)) * LDK + (lane >> 4) * 8) * 2);
    const unsigned boff = (unsigned)(((warpCol + (lane & 7)) * LDK + ((lane >> 3) & 1) * 8) * 2);

    float acc[4][4][4];
#pragma unroll
    for (int i = 0; i < 4; i++)
#pragma unroll
        for (int j = 0; j < 4; j++)
#pragma unroll
            for (int q = 0; q < 4; q++) acc[i][j][q] = 0.f;

    for (int kk = 0; kk < DIM; kk += 32) {
        // ---- stage: 2048 x 16B chunks (A hi/lo + B hi/lo), 8 per thread ----
#pragma unroll
        for (int i = 0; i < 8; i++) {
            int flat = i * 256 + tid;
            int ch = flat & 3;
            int row = (flat >> 2) & 127;
            int hl = (flat >> 9) & 1;
            int ab = flat >> 10;
            unsigned dst = sbase + (unsigned)(((ab * 2 + hl) * TILE)
                                              + row * LDK + ch * 8) * 2u;
            const __nv_bfloat16* src;
            int ok = 1;
            if (ab == 0) {
                int gr = rowBase + row;
                ok = (gr < M); if (!ok) gr = 0;
                src = (hl ? Alo : Ahi) + (size_t)gr * DIM + kk + ch * 8;
            } else {
                int gc = colBase + row;                    // Ncols always mult of 128
                src = (hl ? Blo : Bhi) + (size_t)gc * DIM + kk + ch * 8;
            }
            cpasync16(dst, src, ok ? 16 : 0);
        }
        asm volatile("cp.async.commit_group;");
        asm volatile("cp.async.wait_group 0;");
        __syncthreads();

        const unsigned aHi = sbase;
        const unsigned aLo = sbase + (unsigned)TILE * 2u;
        const unsigned bHi = sbase + (unsigned)(2 * TILE) * 2u;
        const unsigned bLo = sbase + (unsigned)(3 * TILE) * 2u;
#pragma unroll
        for (int ks = 0; ks < 2; ks++) {
            unsigned kb = ks * 32;      // 16 bf16 = 32B
            unsigned af[4][4], bh[4][2], bl[4][2];
#pragma unroll
            for (int i = 0; i < 4; i++) ldmx4(af[i], aHi + aoff + kb + i * 16 * LDK * 2);
#pragma unroll
            for (int j = 0; j < 4; j++) ldmx2(bh[j], bHi + boff + kb + j * 8 * LDK * 2);
#pragma unroll
            for (int j = 0; j < 4; j++) ldmx2(bl[j], bLo + boff + kb + j * 8 * LDK * 2);
#pragma unroll
            for (int i = 0; i < 4; i++)
#pragma unroll
                for (int j = 0; j < 4; j++) mma16816(acc[i][j], af[i], bh[j]);  // hi*hi
#pragma unroll
            for (int i = 0; i < 4; i++)
#pragma unroll
                for (int j = 0; j < 4; j++) mma16816(acc[i][j], af[i], bl[j]);  // hi*lo
#pragma unroll
            for (int i = 0; i < 4; i++) ldmx4(af[i], aLo + aoff + kb + i * 16 * LDK * 2);
#pragma unroll
            for (int i = 0; i < 4; i++)
#pragma unroll
                for (int j = 0; j < 4; j++) mma16816(acc[i][j], af[i], bh[j]);  // lo*hi
        }
        __syncthreads();
    }

    // ---- epilogue: fp32 + optional bias ----
    const int rr = lane >> 2, cc = (lane & 3) * 2;
#pragma unroll
    for (int i = 0; i < 4; i++) {
        int gr0 = rowBase + warpRow + i * 16 + rr;
#pragma unroll
        for (int j = 0; j < 4; j++) {
            int gc = colBase + warpCol + j * 8 + cc;
            float b0 = bp ? bp[gc] : 0.f;
            float b1 = bp ? bp[gc + 1] : 0.f;
            if (gr0 < M) {
                C[(size_t)gr0 * Ncols + gc]     = acc[i][j][0] + b0;
                C[(size_t)gr0 * Ncols + gc + 1] = acc[i][j][1] + b1;
            }
            if (gr0 + 8 < M) {
                C[(size_t)(gr0 + 8) * Ncols + gc]     = acc[i][j][2] + b0;
                C[(size_t)(gr0 + 8) * Ncols + gc + 1] = acc[i][j][3] + b1;
            }
        }
    }
}

// ---------------- split helper ----------------
__global__ void split_kernel(const float* __restrict__ s, __nv_bfloat16* __restrict__ hi,
                             __nv_bfloat16* __restrict__ lo, int n) {
    int i = blockIdx.x * blockDim.x + threadIdx.x;
    if (i < n) {
        float v = s[i];
        __nv_bfloat16 h = __float2bfloat16(v);
        hi[i] = h;
        lo[i] = __float2bfloat16(v - __bfloat162float(h));
    }
}

// ---------------- CSR construction ----------------
__global__ void zero_int_kernel(int* p, int n) {
    int i = blockIdx.x * blockDim.x + threadIdx.x;
    if (i < n) p[i] = 0;
}
__global__ void hist_kernel(const int* __restrict__ dst, int* deg, int E) {
    int i = blockIdx.x * blockDim.x + threadIdx.x;
    if (i < E) atomicAdd(&deg[dst[i]], 1);
}
__global__ void scan_kernel(const int* __restrict__ deg, int* off, int* cur, int n) {
    __shared__ int tmp[1024];
    __shared__ int carry_s;
    int t = threadIdx.x;
    if (t == 0) { off[0] = 0; cur[0] = 0; carry_s = 0; }
    __syncthreads();
    for (int base = 0; base < n; base += 1024) {
        int v = (base + t < n) ? deg[base + t] : 0;
        tmp[t] = v;
        __syncthreads();
        for (int s = 1; s < 1024; s <<= 1) {
            int x = (t >= s) ? tmp[t - s] : 0;
            __syncthreads();
            tmp[t] += x;
            __syncthreads();
        }
        int incl = tmp[t] + carry_s;
        if (base + t < n) { off[base + t + 1] = incl; cur[base + t + 1] = incl; }
        __syncthreads();
        if (t == 1023) carry_s = incl;
        __syncthreads();
    }
}
__global__ void scatter_kernel(const int* __restrict__ src, const int* __restrict__ dst,
                               const int* __restrict__ et, int* cur,
                               int* cgidx, int* csrc, int E, int n) {
    int i = blockIdx.x * blockDim.x + threadIdx.x;
    if (i >= E) return;
    int d = dst[i];
    int p = atomicAdd(&cur[d], 1);
    int s = src[i];
    cgidx[p] = et[i] * n + s;
    csrc[p]  = s;
}

// ---------------- GGC: message aggregation -> 'a' split bf16 ----------------
__global__ void agg_kernel(const int* __restrict__ off, const int* __restrict__ cgidx,
                           const float* __restrict__ t,
                           __nv_bfloat16* __restrict__ ah, __nv_bfloat16* __restrict__ al) {
    int n = blockIdx.x, tid = threadIdx.x;  // 128 threads = features
    int s = off[n], e = off[n + 1];
    float acc = 0.f;
    for (int i = s; i < e; i++) {
        int g = __ldg(&cgidx[i]);
        acc += __ldg(&t[(size_t)g * DIM + tid]);
    }
    __nv_bfloat16 hh = __float2bfloat16(acc);
    ah[(size_t)n * DIM + tid] = hh;
    al[(size_t)n * DIM + tid] = __float2bfloat16(acc - __bfloat162float(hh));
}

// ---------------- GRU elementwise (+ h split output) ----------------
__global__ void gru_kernel(const float* __restrict__ gi, const float* __restrict__ gh,
                           const float* __restrict__ hold, float* __restrict__ hnew,
                           __nv_bfloat16* __restrict__ hbh, __nv_bfloat16* __restrict__ hbl,
                           int n) {
    int idx = blockIdx.x * blockDim.x + threadIdx.x;
    if (idx >= n * DIM) return;
    int node = idx >> 7, d = idx & 127;
    const float* gip = gi + (size_t)node * 384;
    const float* ghp = gh + (size_t)node * 384;
    float r  = 1.f / (1.f + expf(-(gip[d] + ghp[d])));
    float zq = 1.f / (1.f + expf(-(gip[128 + d] + ghp[128 + d])));
    float nn = tanhf(gip[256 + d] + r * ghp[256 + d]);
    float h0 = hold[idx];
    float hv = (1.f - zq) * nn + zq * h0;
    hnew[idx] = hv;
    __nv_bfloat16 hh = __float2bfloat16(hv);
    hbh[idx] = hh;
    hbl[idx] = __float2bfloat16(hv - __bfloat162float(hh));
}

// ---------------- L2 normalize + sigmoid -> split bf16 ----------------
__global__ void normsig_kernel(const float* __restrict__ h,
                               __nv_bfloat16* __restrict__ hbh, __nv_bfloat16* __restrict__ hbl) {
    int n = blockIdx.x, tid = threadIdx.x;  // 128
    __shared__ float red[128];
    float v = h[(size_t)n * DIM + tid];
    red[tid] = v * v;
    __syncthreads();
    for (int s = 64; s; s >>= 1) {
        if (tid < s) red[tid] += red[tid + s];
        __syncthreads();
    }
    float norm = fmaxf(sqrtf(red[0]), 1e-12f);
    float x = 1.f / (1.f + expf(-(v / norm)));
    __nv_bfloat16 hh = __float2bfloat16(x);
    hbh[(size_t)n * DIM + tid] = hh;
    hbl[(size_t)n * DIM + tid] = __float2bfloat16(x - __bfloat162float(hh));
}

// ---------------- GAT: el/er per node ----------------
__global__ void eler_kernel(const float* __restrict__ z, const float* __restrict__ al,
                            const float* __restrict__ ar, float* __restrict__ el,
                            float* __restrict__ er) {
    int n = blockIdx.x, tid = threadIdx.x;  // 256 = (head, d)
    __shared__ float sl[256], sr[256];
    float zv = z[(size_t)n * 256 + tid];
    sl[tid] = zv * al[tid];
    sr[tid] = zv * ar[tid];
    __syncthreads();
    int lane = tid & 127;
    for (int s = 64; s; s >>= 1) {
        if (lane < s) { sl[tid] += sl[tid + s]; sr[tid] += sr[tid + s]; }
        __syncthreads();
    }
    if (lane == 0) {
        int h = tid >> 7;
        el[n * 2 + h] = sl[tid];
        er[n * 2 + h] = sr[tid];
    }
}

// ---------------- GAT: edge softmax + weighted aggregation ----------------
__global__ void gat_kernel(const int* __restrict__ off, const int* __restrict__ csrc,
                           const float* __restrict__ el, const float* __restrict__ er,
                           const float* __restrict__ z, const float* __restrict__ bias,
                           float* __restrict__ outp) {
    int n = blockIdx.x, tid = threadIdx.x;  // 256 = (head, d)
    int h = tid >> 7, lane = tid & 127;
    int s0 = off[n], s1 = off[n + 1];
    float er_nh = er[n * 2 + h];

    __shared__ float red[256];
    __shared__ float mden[4];
    __shared__ float wbuf[2][128];
    __shared__ int   sbuf[128];

    float lmax = -3.0e38f;
    for (int e = s0 + lane; e < s1; e += 128) {
        float x = el[csrc[e] * 2 + h] + er_nh;
        x = x > 0.f ? x : 0.2f * x;
        lmax = fmaxf(lmax, x);
    }
    red[tid] = lmax;
    __syncthreads();
    for (int s = 64; s; s >>= 1) {
        if (lane < s) red[tid] = fmaxf(red[tid], red[tid + s]);
        __syncthreads();
    }
    if (lane == 0) mden[h] = red[tid];
    __syncthreads();
    float m = mden[h];

    float lsum = 0.f;
    for (int e = s0 + lane; e < s1; e += 128) {
        float x = el[csrc[e] * 2 + h] + er_nh;
        x = x > 0.f ? x : 0.2f * x;
        lsum += expf(x - m);
    }
    red[tid] = lsum;
    __syncthreads();
    for (int s = 64; s; s >>= 1) {
        if (lane < s) red[tid] += red[tid + s];
        __syncthreads();
    }
    if (lane == 0) mden[2 + h] = 1.f / red[tid];
    __syncthreads();
    float invden = mden[2 + h];

    float acc = 0.f;
    for (int base = s0; base < s1; base += 128) {
        int cnt = min(128, s1 - base);
        if (lane < cnt) {
            int sn = csrc[base + lane];
            float x = el[sn * 2 + h] + er_nh;
            x = x > 0.f ? x : 0.2f * x;
            wbuf[h][lane] = expf(x - m) * invden;
            if (h == 0) sbuf[lane] = sn;
        }
        __syncthreads();
        for (int i = 0; i < cnt; i++)
            acc = fmaf(wbuf[h][i], z[(size_t)sbuf[i] * 256 + tid], acc);
        __syncthreads();
    }
    float o = acc + bias[tid];
    outp[(size_t)n * 256 + tid] = fmaxf(o, 0.f);
}

// ---------------- graph mean-pool ----------------
__global__ void pool_kernel(const int* __restrict__ gid, const float* __restrict__ hgat,
                            float* __restrict__ hg, int n) {
    int b = blockIdx.x, tid = threadIdx.x;  // 256
    __shared__ int s_lo, s_hi;
    if (tid == 0) {
        int lo = 0, hi = n;
        while (lo < hi) { int mid = (lo + hi) >> 1; if (gid[mid] < b) lo = mid + 1; else hi = mid; }
        s_lo = lo;
        lo = 0; hi = n;
        while (lo < hi) { int mid = (lo + hi) >> 1; if (gid[mid] < b + 1) lo = mid + 1; else hi = mid; }
        s_hi = lo;
    }
    __syncthreads();
    float acc = 0.f;
    for (int node = s_lo; node < s_hi; node++)
        acc += hgat[(size_t)node * 256 + tid];
    float cnt = (float)(s_hi - s_lo);
    hg[b * 256 + tid] = acc / fmaxf(cnt, 1.f);
}

// ---------------- classifier ----------------
__global__ void cls_kernel(const float* __restrict__ hg, const float* __restrict__ Wc,
                           const float* __restrict__ bc, float* __restrict__ outc) {
    int b = blockIdx.x, tid = threadIdx.x;  // 64 = (head, c)
    __shared__ float sh[256];
    for (int i = tid; i < 256; i += 64) sh[i] = hg[b * 256 + i];
    __syncthreads();
    int h = tid >> 5, c = tid & 31;
    float s = bc[c];
    for (int d = 0; d < DIM; d++)
        s = fmaf(sh[h * 128 + d], Wc[c * 128 + d], s);
    outc[b * 64 + tid] = s;
}

// ---------------- pairwise distance + softmax over heads ----------------
__global__ void final_kernel(const float* __restrict__ c1, const float* __restrict__ c2,
                             float* __restrict__ out) {
    int b = threadIdx.x;
    if (b >= NGR) return;
    float dist[2];
    for (int h = 0; h < 2; h++) {
        float ss = 0.f;
        for (int c = 0; c < 32; c++) {
            float diff = c1[b * 64 + h * 32 + c] - c2[b * 64 + h * 32 + c] + 1e-6f;
            ss += diff * diff;
        }
        dist[h] = sqrtf(ss);
    }
    float mx = fmaxf(dist[0], dist[1]);
    float e0 = expf(dist[0] - mx), e1 = expf(dist[1] - mx);
    float inv = 1.f / (e0 + e1);
    out[b * 2 + 0] = e0 * inv;
    out[b * 2 + 1] = e1 * inv;
}

// ---------------- host launcher ----------------
extern "C" void kernel_launch(void* const* d_in, const int* in_sizes, int n_in,
                              void* d_out, int out_size) {
    const float* feat[2] = {(const float*)d_in[0], (const float*)d_in[1]};
    const int* srcs[2] = {(const int*)d_in[2], (const int*)d_in[6]};
    const int* dsts[2] = {(const int*)d_in[3], (const int*)d_in[7]};
    const int* ets[2]  = {(const int*)d_in[4], (const int*)d_in[8]};
    const int* gids[2] = {(const int*)d_in[5], (const int*)d_in[9]};
    const float* W_et   = (const float*)d_in[10];
    const float* b_et   = (const float*)d_in[11];
    const float* W_ih   = (const float*)d_in[12];
    const float* W_hh   = (const float*)d_in[13];
    const float* b_ih   = (const float*)d_in[14];
    const float* b_hh   = (const float*)d_in[15];
    const float* W_fc   = (const float*)d_in[16];
    const float* attn_l = (const float*)d_in[17];
    const float* attn_r = (const float*)d_in[18];
    const float* g_bias = (const float*)d_in[19];
    const float* W_cls  = (const float*)d_in[20];
    const float* b_cls  = (const float*)d_in[21];

    int N = in_sizes[0] / DIM;
    int E = in_sizes[2];

    float *t, *h, *gi, *gh, *z, *gat, *el, *er, *hg, *cls;
    int *deg, *off, *cur, *cgidx, *csrc;
    __nv_bfloat16 *ah, *al, *hbh, *hbl;
    __nv_bfloat16 *weth, *wetl, *wihh, *wihl, *whhh, *whhl, *wfch, *wfcl;
    cudaGetSymbolAddress((void**)&t, g_t);
    cudaGetSymbolAddress((void**)&h, g_h);
    cudaGetSymbolAddress((void**)&gi, g_gi);
    cudaGetSymbolAddress((void**)&gh, g_gh);
    cudaGetSymbolAddress((void**)&z, g_z);
    cudaGetSymbolAddress((void**)&gat, g_gat);
    cudaGetSymbolAddress((void**)&el, g_el);
    cudaGetSymbolAddress((void**)&er, g_er);
    cudaGetSymbolAddress((void**)&deg, g_deg);
    cudaGetSymbolAddress((void**)&off, g_off);
    cudaGetSymbolAddress((void**)&cur, g_cur);
    cudaGetSymbolAddress((void**)&cgidx, g_cgidx);
    cudaGetSymbolAddress((void**)&csrc, g_csrc);
    cudaGetSymbolAddress((void**)&hg, g_hg);
    cudaGetSymbolAddress((void**)&cls, g_cls);
    cudaGetSymbolAddress((void**)&ah, g_ah);
    cudaGetSymbolAddress((void**)&al, g_al);
    cudaGetSymbolAddress((void**)&hbh, g_hbh);
    cudaGetSymbolAddress((void**)&hbl, g_hbl);
    cudaGetSymbolAddress((void**)&weth, g_weth);
    cudaGetSymbolAddress((void**)&wetl, g_wetl);
    cudaGetSymbolAddress((void**)&wihh, g_wihh);
    cudaGetSymbolAddress((void**)&wihl, g_wihl);
    cudaGetSymbolAddress((void**)&whhh, g_whhh);
    cudaGetSymbolAddress((void**)&whhl, g_whhl);
    cudaGetSymbolAddress((void**)&wfch, g_wfch);
    cudaGetSymbolAddress((void**)&wfcl, g_wfcl);

    // split weights (once per launch; tiny)
    split_kernel<<<(NET * 128 * 128 + 255) / 256, 256>>>(W_et, weth, wetl, NET * 128 * 128);
    split_kernel<<<(384 * 128 + 255) / 256, 256>>>(W_ih, wihh, wihl, 384 * 128);
    split_kernel<<<(384 * 128 + 255) / 256, 256>>>(W_hh, whhh, whhl, 384 * 128);
    split_kernel<<<(256 * 128 + 255) / 256, 256>>>(W_fc, wfch, wfcl, 256 * 128);

    int mblocks = (N + 127) / 128;

    for (int g = 0; g < 2; g++) {
        // CSR by dst
        zero_int_kernel<<<(N + 255) / 256, 256>>>(deg, N);
        hist_kernel<<<(E + 255) / 256, 256>>>(dsts[g], deg, E);
        scan_kernel<<<1, 1024>>>(deg, off, cur, N);
        scatter_kernel<<<(E + 255) / 256, 256>>>(srcs[g], dsts[g], ets[g], cur, cgidx, csrc, E, N);

        // split initial features
        split_kernel<<<(N * DIM + 255) / 256, 256>>>(feat[g], hbh, hbl, N * DIM);

        const float* hcur = feat[g];
        for (int s = 0; s < NSTEPS; s++) {
            // t[k] = h @ W_et[k]^T + b_et[k]   (batched over etypes via z)
            bgemm<<<dim3(1, mblocks, NET), 256>>>(hbh, hbl, weth, wetl, b_et, t,
                                                  N, DIM, DIM * DIM, N * DIM, DIM);
            // a = segment_sum(t[etype,src], dst)  -> split bf16
            agg_kernel<<<N, DIM>>>(off, cgidx, t, ah, al);
            // gi = a @ W_ih^T + b_ih ; gh = h @ W_hh^T + b_hh
            bgemm<<<dim3(3, mblocks, 1), 256>>>(ah, al, wihh, wihl, b_ih, gi, N, 3 * DIM, 0, 0, 0);
            bgemm<<<dim3(3, mblocks, 1), 256>>>(hbh, hbl, whhh, whhl, b_hh, gh, N, 3 * DIM, 0, 0, 0);
            gru_kernel<<<(N * DIM + 255) / 256, 256>>>(gi, gh, hcur, h, hbh, hbl, N);
            hcur = h;
        }

        normsig_kernel<<<N, DIM>>>(h, hbh, hbl);

        // GAT: z = h @ W_fc^T
        bgemm<<<dim3(2, mblocks, 1), 256>>>(hbh, hbl, wfch, wfcl, nullptr, z, N, 2 * DIM, 0, 0, 0);
        eler_kernel<<<N, 256>>>(z, attn_l, attn_r, el, er);
        gat_kernel<<<N, 256>>>(off, csrc, el, er, z, g_bias, gat);

        // pool + classify
        pool_kernel<<<NGR, 256>>>(gids[g], gat, hg, N);
        cls_kernel<<<NGR, 64>>>(hg, W_cls, b_cls, cls + g * NGR * 64);
    }

    final_kernel<<<1, 64>>>(cls, cls + NGR * 64, (float*)d_out);
}

// round 13
// speedup vs baseline: 1.7944x; 1.2326x over previous
#include <cuda_runtime.h>
#include <cuda_fp16.h>
#include <math.h>
#include <stdint.h>

// ---------------- problem constants ----------------
#define NNODES 50000
#define NEDGES 600000
#define DIM    128
#define NET    4
#define NSTEPS 5
#define NGR    64

// ---------------- scratch (device globals; no allocation allowed) ----------------
__device__ __align__(128) float g_t[NET * NNODES * DIM];   // per-etype transformed feats (fp32)
__device__ __align__(128) float g_h[NNODES * DIM];
__device__ __align__(128) float g_gi[NNODES * 3 * DIM];
__device__ __align__(128) float g_gh[NNODES * 3 * DIM];
__device__ __align__(128) float g_z[NNODES * 2 * DIM];
__device__ __align__(128) float g_gat[NNODES * 2 * DIM];
__device__ float g_el[NNODES * 2];
__device__ float g_er[NNODES * 2];
__device__ int   g_deg[NNODES];
__device__ int   g_off[NNODES + 1];
__device__ int   g_cur[NNODES + 1];
__device__ int   g_cgidx[NEDGES];                // etype*N + src, dst-sorted
__device__ int   g_csrc[NEDGES];                 // src, dst-sorted
__device__ float g_hg[NGR * 2 * DIM];
__device__ float g_cls[2 * NGR * 64];

// fp16 activation / weight buffers
__device__ __align__(128) __half g_a16[NNODES * DIM];      // aggregated messages
__device__ __align__(128) __half g_h16[NNODES * DIM];      // hidden state
__device__ __align__(128) __half g_wet16[NET * DIM * DIM];
__device__ __align__(128) __half g_wih16[384 * DIM];
__device__ __align__(128) __half g_whh16[384 * DIM];
__device__ __align__(128) __half g_wfc16[256 * DIM];

// =====================================================================
// fp16 tensor-core GEMM (single pass, fp32 accumulate):
//   C[m,c] = sum_k A[m,k]*B[c,k] + bias[c]     (K = 128 fixed)
// A [M,128] f16 row-major, B [Ncols,128] f16 row-major.
// Block tile 128x128, 8 warps of 64x32, BK=32, cp.async + ldmatrix.
// blockIdx.z batches B/C/bias (the 4 etype weights).
// =====================================================================
#define LDK  40                    // padded f16 row: 80B, conflict-free LDSM
#define TILEH (128 * LDK)

__device__ __forceinline__ void mma16816(float* c, const unsigned* a, const unsigned* b) {
    asm volatile(
        "mma.sync.aligned.m16n8k16.row.col.f32.f16.f16.f32 "
        "{%0,%1,%2,%3},{%4,%5,%6,%7},{%8,%9},{%0,%1,%2,%3};"
        : "+f"(c[0]), "+f"(c[1]), "+f"(c[2]), "+f"(c[3])
        : "r"(a[0]), "r"(a[1]), "r"(a[2]), "r"(a[3]), "r"(b[0]), "r"(b[1]));
}
__device__ __forceinline__ void ldmx4(unsigned* r, unsigned addr) {
    asm volatile("ldmatrix.sync.aligned.m8n8.x4.shared.b16 {%0,%1,%2,%3}, [%4];"
                 : "=r"(r[0]), "=r"(r[1]), "=r"(r[2]), "=r"(r[3]) : "r"(addr));
}
__device__ __forceinline__ void ldmx2(unsigned* r, unsigned addr) {
    asm volatile("ldmatrix.sync.aligned.m8n8.x2.shared.b16 {%0,%1}, [%2];"
                 : "=r"(r[0]), "=r"(r[1]) : "r"(addr));
}
__device__ __forceinline__ void cpasync16(unsigned dst, const void* src, int sz) {
    asm volatile("cp.async.cg.shared.global [%0], [%1], 16, %2;"
                 :: "r"(dst), "l"(src), "r"(sz));
}

__global__ __launch_bounds__(256) void hgemm(
    const __half* __restrict__ A, const __half* __restrict__ B,
    const float* __restrict__ bias, float* __restrict__ C,
    int M, int Ncols, int strideB, int strideC, int strideBias)
{
    __shared__ __align__(16) __half S[2][128][LDK];   // A, B tiles

    const int bz = blockIdx.z;
    B += (size_t)bz * strideB;
    C += (size_t)bz * strideC;
    const float* bp = bias ? (bias + (size_t)bz * strideBias) : nullptr;

    const int tid = threadIdx.x;
    const int rowBase = blockIdx.y * 128, colBase = blockIdx.x * 128;
    const unsigned sbase = (unsigned)__cvta_generic_to_shared(&S[0][0][0]);

    const int lane = tid & 31, warp = tid >> 5;
    const int warpRow = (warp >> 2) * 64, warpCol = (warp & 3) * 32;
    const unsigned aoff = (unsigned)(((warpRow + (lane & 15)) * LDK + (lane >> 4) * 8) * 2);
    const unsigned boff = (unsigned)(((warpCol + (lane & 7)) * LDK + ((lane >> 3) & 1) * 8) * 2);

    float acc[4][4][4];
#pragma unroll
    for (int i = 0; i < 4; i++)
#pragma unroll
        for (int j = 0; j < 4; j++)
#pragma unroll
            for (int q = 0; q < 4; q++) acc[i][j][q] = 0.f;

    for (int kk = 0; kk < DIM; kk += 32) {
        // ---- stage: 1024 x 16B chunks (A + B), 4 per thread ----
#pragma unroll
        for (int i = 0; i < 4; i++) {
            int flat = i * 256 + tid;           // 0..1023
            int ab = flat >> 9;                 // 0 = A, 1 = B
            int rem = flat & 511;
            int row = rem >> 2, ch = rem & 3;   // row 0..127, chunk 0..3
            unsigned dst = sbase + (unsigned)(ab * TILEH + row * LDK + ch * 8) * 2u;
            const __half* src;
            int ok = 1;
            if (ab == 0) {
                int gr = rowBase + row;
                ok = (gr < M); if (!ok) gr = 0;
                src = A + (size_t)gr * DIM + kk + ch * 8;
            } else {
                int gc = colBase + row;         // Ncols always a multiple of 128
                src = B + (size_t)gc * DIM + kk + ch * 8;
            }
            cpasync16(dst, src, ok ? 16 : 0);
        }
        asm volatile("cp.async.commit_group;");
        asm volatile("cp.async.wait_group 0;");
        __syncthreads();

        const unsigned aB = sbase;
        const unsigned bB = sbase + (unsigned)TILEH * 2u;
#pragma unroll
        for (int ks = 0; ks < 2; ks++) {
            unsigned kb = ks * 32;              // 16 f16 = 32B
            unsigned af[4][4], bf[4][2];
#pragma unroll
            for (int i = 0; i < 4; i++) ldmx4(af[i], aB + aoff + kb + i * 16 * LDK * 2);
#pragma unroll
            for (int j = 0; j < 4; j++) ldmx2(bf[j], bB + boff + kb + j * 8 * LDK * 2);
#pragma unroll
            for (int i = 0; i < 4; i++)
#pragma unroll
                for (int j = 0; j < 4; j++) mma16816(acc[i][j], af[i], bf[j]);
        }
        __syncthreads();
    }

    // ---- epilogue: fp32 + optional bias ----
    const int rr = lane >> 2, cc = (lane & 3) * 2;
#pragma unroll
    for (int i = 0; i < 4; i++) {
        int gr0 = rowBase + warpRow + i * 16 + rr;
#pragma unroll
        for (int j = 0; j < 4; j++) {
            int gc = colBase + warpCol + j * 8 + cc;
            float b0 = bp ? bp[gc] : 0.f;
            float b1 = bp ? bp[gc + 1] : 0.f;
            if (gr0 < M) {
                C[(size_t)gr0 * Ncols + gc]     = acc[i][j][0] + b0;
                C[(size_t)gr0 * Ncols + gc + 1] = acc[i][j][1] + b1;
            }
            if (gr0 + 8 < M) {
                C[(size_t)(gr0 + 8) * Ncols + gc]     = acc[i][j][2] + b0;
                C[(size_t)(gr0 + 8) * Ncols + gc + 1] = acc[i][j][3] + b1;
            }
        }
    }
}

// ---------------- fp32 -> fp16 convert ----------------
__global__ void cvt_kernel(const float* __restrict__ s, __half* __restrict__ d, int n) {
    int i = blockIdx.x * blockDim.x + threadIdx.x;
    if (i < n) d[i] = __float2half(s[i]);
}

// ---------------- CSR construction ----------------
__global__ void zero_int_kernel(int* p, int n) {
    int i = blockIdx.x * blockDim.x + threadIdx.x;
    if (i < n) p[i] = 0;
}
__global__ void hist_kernel(const int* __restrict__ dst, int* deg, int E) {
    int i = blockIdx.x * blockDim.x + threadIdx.x;
    if (i < E) atomicAdd(&deg[dst[i]], 1);
}
__global__ void scan_kernel(const int* __restrict__ deg, int* off, int* cur, int n) {
    __shared__ int tmp[1024];
    __shared__ int carry_s;
    int t = threadIdx.x;
    if (t == 0) { off[0] = 0; cur[0] = 0; carry_s = 0; }
    __syncthreads();
    for (int base = 0; base < n; base += 1024) {
        int v = (base + t < n) ? deg[base + t] : 0;
        tmp[t] = v;
        __syncthreads();
        for (int s = 1; s < 1024; s <<= 1) {
            int x = (t >= s) ? tmp[t - s] : 0;
            __syncthreads();
            tmp[t] += x;
            __syncthreads();
        }
        int incl = tmp[t] + carry_s;
        if (base + t < n) { off[base + t + 1] = incl; cur[base + t + 1] = incl; }
        __syncthreads();
        if (t == 1023) carry_s = incl;
        __syncthreads();
    }
}
__global__ void scatter_kernel(const int* __restrict__ src, const int* __restrict__ dst,
                               const int* __restrict__ et, int* cur,
                               int* cgidx, int* csrc, int E, int n) {
    int i = blockIdx.x * blockDim.x + threadIdx.x;
    if (i >= E) return;
    int d = dst[i];
    int p = atomicAdd(&cur[d], 1);
    int s = src[i];
    cgidx[p] = et[i] * n + s;
    csrc[p]  = s;
}

// ---------------- GGC: message aggregation -> 'a' fp16 ----------------
__global__ void agg_kernel(const int* __restrict__ off, const int* __restrict__ cgidx,
                           const float* __restrict__ t, __half* __restrict__ a16) {
    int n = blockIdx.x, tid = threadIdx.x;  // 128 threads = features
    int s = off[n], e = off[n + 1];
    float acc = 0.f;
    for (int i = s; i < e; i++) {
        int g = __ldg(&cgidx[i]);
        acc += __ldg(&t[(size_t)g * DIM + tid]);
    }
    a16[(size_t)n * DIM + tid] = __float2half(acc);
}

// ---------------- GRU elementwise (+ fp16 h output) ----------------
__global__ void gru_kernel(const float* __restrict__ gi, const float* __restrict__ gh,
                           const float* __restrict__ hold, float* __restrict__ hnew,
                           __half* __restrict__ h16, int n) {
    int idx = blockIdx.x * blockDim.x + threadIdx.x;
    if (idx >= n * DIM) return;
    int node = idx >> 7, d = idx & 127;
    const float* gip = gi + (size_t)node * 384;
    const float* ghp = gh + (size_t)node * 384;
    float r  = 1.f / (1.f + expf(-(gip[d] + ghp[d])));
    float zq = 1.f / (1.f + expf(-(gip[128 + d] + ghp[128 + d])));
    float nn = tanhf(gip[256 + d] + r * ghp[256 + d]);
    float h0 = hold[idx];
    float hv = (1.f - zq) * nn + zq * h0;
    hnew[idx] = hv;
    h16[idx] = __float2half(hv);
}

// ---------------- L2 normalize + sigmoid -> fp16 ----------------
__global__ void normsig_kernel(const float* __restrict__ h, __half* __restrict__ h16) {
    int n = blockIdx.x, tid = threadIdx.x;  // 128
    __shared__ float red[128];
    float v = h[(size_t)n * DIM + tid];
    red[tid] = v * v;
    __syncthreads();
    for (int s = 64; s; s >>= 1) {
        if (tid < s) red[tid] += red[tid + s];
        __syncthreads();
    }
    float norm = fmaxf(sqrtf(red[0]), 1e-12f);
    float x = 1.f / (1.f + expf(-(v / norm)));
    h16[(size_t)n * DIM + tid] = __float2half(x);
}

// ---------------- GAT: el/er per node ----------------
__global__ void eler_kernel(const float* __restrict__ z, const float* __restrict__ al,
                            const float* __restrict__ ar, float* __restrict__ el,
                            float* __restrict__ er) {
    int n = blockIdx.x, tid = threadIdx.x;  // 256 = (head, d)
    __shared__ float sl[256], sr[256];
    float zv = z[(size_t)n * 256 + tid];
    sl[tid] = zv * al[tid];
    sr[tid] = zv * ar[tid];
    __syncthreads();
    int lane = tid & 127;
    for (int s = 64; s; s >>= 1) {
        if (lane < s) { sl[tid] += sl[tid + s]; sr[tid] += sr[tid + s]; }
        __syncthreads();
    }
    if (lane == 0) {
        int h = tid >> 7;
        el[n * 2 + h] = sl[tid];
        er[n * 2 + h] = sr[tid];
    }
}

// ---------------- GAT: edge softmax + weighted aggregation ----------------
__global__ void gat_kernel(const int* __restrict__ off, const int* __restrict__ csrc,
                           const float* __restrict__ el, const float* __restrict__ er,
                           const float* __restrict__ z, const float* __restrict__ bias,
                           float* __restrict__ outp) {
    int n = blockIdx.x, tid = threadIdx.x;  // 256 = (head, d)
    int h = tid >> 7, lane = tid & 127;
    int s0 = off[n], s1 = off[n + 1];
    float er_nh = er[n * 2 + h];

    __shared__ float red[256];
    __shared__ float mden[4];
    __shared__ float wbuf[2][128];
    __shared__ int   sbuf[128];

    float lmax = -3.0e38f;
    for (int e = s0 + lane; e < s1; e += 128) {
        float x = el[csrc[e] * 2 + h] + er_nh;
        x = x > 0.f ? x : 0.2f * x;
        lmax = fmaxf(lmax, x);
    }
    red[tid] = lmax;
    __syncthreads();
    for (int s = 64; s; s >>= 1) {
        if (lane < s) red[tid] = fmaxf(red[tid], red[tid + s]);
        __syncthreads();
    }
    if (lane == 0) mden[h] = red[tid];
    __syncthreads();
    float m = mden[h];

    float lsum = 0.f;
    for (int e = s0 + lane; e < s1; e += 128) {
        float x = el[csrc[e] * 2 + h] + er_nh;
        x = x > 0.f ? x : 0.2f * x;
        lsum += expf(x - m);
    }
    red[tid] = lsum;
    __syncthreads();
    for (int s = 64; s; s >>= 1) {
        if (lane < s) red[tid] += red[tid + s];
        __syncthreads();
    }
    if (lane == 0) mden[2 + h] = 1.f / red[tid];
    __syncthreads();
    float invden = mden[2 + h];

    float acc = 0.f;
    for (int base = s0; base < s1; base += 128) {
        int cnt = min(128, s1 - base);
        if (lane < cnt) {
            int sn = csrc[base + lane];
            float x = el[sn * 2 + h] + er_nh;
            x = x > 0.f ? x : 0.2f * x;
            wbuf[h][lane] = expf(x - m) * invden;
            if (h == 0) sbuf[lane] = sn;
        }
        __syncthreads();
        for (int i = 0; i < cnt; i++)
            acc = fmaf(wbuf[h][i], z[(size_t)sbuf[i] * 256 + tid], acc);
        __syncthreads();
    }
    float o = acc + bias[tid];
    outp[(size_t)n * 256 + tid] = fmaxf(o, 0.f);
}

// ---------------- graph mean-pool ----------------
__global__ void pool_kernel(const int* __restrict__ gid, const float* __restrict__ hgat,
                            float* __restrict__ hg, int n) {
    int b = blockIdx.x, tid = threadIdx.x;  // 256
    __shared__ int s_lo, s_hi;
    if (tid == 0) {
        int lo = 0, hi = n;
        while (lo < hi) { int mid = (lo + hi) >> 1; if (gid[mid] < b) lo = mid + 1; else hi = mid; }
        s_lo = lo;
        lo = 0; hi = n;
        while (lo < hi) { int mid = (lo + hi) >> 1; if (gid[mid] < b + 1) lo = mid + 1; else hi = mid; }
        s_hi = lo;
    }
    __syncthreads();
    float acc = 0.f;
    for (int node = s_lo; node < s_hi; node++)
        acc += hgat[(size_t)node * 256 + tid];
    float cnt = (float)(s_hi - s_lo);
    hg[b * 256 + tid] = acc / fmaxf(cnt, 1.f);
}

// ---------------- classifier ----------------
__global__ void cls_kernel(const float* __restrict__ hg, const float* __restrict__ Wc,
                           const float* __restrict__ bc, float* __restrict__ outc) {
    int b = blockIdx.x, tid = threadIdx.x;  // 64 = (head, c)
    __shared__ float sh[256];
    for (int i = tid; i < 256; i += 64) sh[i] = hg[b * 256 + i];
    __syncthreads();
    int h = tid >> 5, c = tid & 31;
    float s = bc[c];
    for (int d = 0; d < DIM; d++)
        s = fmaf(sh[h * 128 + d], Wc[c * 128 + d], s);
    outc[b * 64 + tid] = s;
}

// ---------------- pairwise distance + softmax over heads ----------------
__global__ void final_kernel(const float* __restrict__ c1, const float* __restrict__ c2,
                             float* __restrict__ out) {
    int b = threadIdx.x;
    if (b >= NGR) return;
    float dist[2];
    for (int h = 0; h < 2; h++) {
        float ss = 0.f;
        for (int c = 0; c < 32; c++) {
            float diff = c1[b * 64 + h * 32 + c] - c2[b * 64 + h * 32 + c] + 1e-6f;
            ss += diff * diff;
        }
        dist[h] = sqrtf(ss);
    }
    float mx = fmaxf(dist[0], dist[1]);
    float e0 = expf(dist[0] - mx), e1 = expf(dist[1] - mx);
    float inv = 1.f / (e0 + e1);
    out[b * 2 + 0] = e0 * inv;
    out[b * 2 + 1] = e1 * inv;
}

// ---------------- host launcher ----------------
extern "C" void kernel_launch(void* const* d_in, const int* in_sizes, int n_in,
                              void* d_out, int out_size) {
    const float* feat[2] = {(const float*)d_in[0], (const float*)d_in[1]};
    const int* srcs[2] = {(const int*)d_in[2], (const int*)d_in[6]};
    const int* dsts[2] = {(const int*)d_in[3], (const int*)d_in[7]};
    const int* ets[2]  = {(const int*)d_in[4], (const int*)d_in[8]};
    const int* gids[2] = {(const int*)d_in[5], (const int*)d_in[9]};
    const float* W_et   = (const float*)d_in[10];
    const float* b_et   = (const float*)d_in[11];
    const float* W_ih   = (const float*)d_in[12];
    const float* W_hh   = (const float*)d_in[13];
    const float* b_ih   = (const float*)d_in[14];
    const float* b_hh   = (const float*)d_in[15];
    const float* W_fc   = (const float*)d_in[16];
    const float* attn_l = (const float*)d_in[17];
    const float* attn_r = (const float*)d_in[18];
    const float* g_bias = (const float*)d_in[19];
    const float* W_cls  = (const float*)d_in[20];
    const float* b_cls  = (const float*)d_in[21];

    int N = in_sizes[0] / DIM;
    int E = in_sizes[2];

    float *t, *h, *gi, *gh, *z, *gat, *el, *er, *hg, *cls;
    int *deg, *off, *cur, *cgidx, *csrc;
    __half *a16, *h16, *wet16, *wih16, *whh16, *wfc16;
    cudaGetSymbolAddress((void**)&t, g_t);
    cudaGetSymbolAddress((void**)&h, g_h);
    cudaGetSymbolAddress((void**)&gi, g_gi);
    cudaGetSymbolAddress((void**)&gh, g_gh);
    cudaGetSymbolAddress((void**)&z, g_z);
    cudaGetSymbolAddress((void**)&gat, g_gat);
    cudaGetSymbolAddress((void**)&el, g_el);
    cudaGetSymbolAddress((void**)&er, g_er);
    cudaGetSymbolAddress((void**)&deg, g_deg);
    cudaGetSymbolAddress((void**)&off, g_off);
    cudaGetSymbolAddress((void**)&cur, g_cur);
    cudaGetSymbolAddress((void**)&cgidx, g_cgidx);
    cudaGetSymbolAddress((void**)&csrc, g_csrc);
    cudaGetSymbolAddress((void**)&hg, g_hg);
    cudaGetSymbolAddress((void**)&cls, g_cls);
    cudaGetSymbolAddress((void**)&a16, g_a16);
    cudaGetSymbolAddress((void**)&h16, g_h16);
    cudaGetSymbolAddress((void**)&wet16, g_wet16);
    cudaGetSymbolAddress((void**)&wih16, g_wih16);
    cudaGetSymbolAddress((void**)&whh16, g_whh16);
    cudaGetSymbolAddress((void**)&wfc16, g_wfc16);

    // convert weights to fp16 (once per launch; tiny)
    cvt_kernel<<<(NET * 128 * 128 + 255) / 256, 256>>>(W_et, wet16, NET * 128 * 128);
    cvt_kernel<<<(384 * 128 + 255) / 256, 256>>>(W_ih, wih16, 384 * 128);
    cvt_kernel<<<(384 * 128 + 255) / 256, 256>>>(W_hh, whh16, 384 * 128);
    cvt_kernel<<<(256 * 128 + 255) / 256, 256>>>(W_fc, wfc16, 256 * 128);

    int mblocks = (N + 127) / 128;

    for (int g = 0; g < 2; g++) {
        // CSR by dst
        zero_int_kernel<<<(N + 255) / 256, 256>>>(deg, N);
        hist_kernel<<<(E + 255) / 256, 256>>>(dsts[g], deg, E);
        scan_kernel<<<1, 1024>>>(deg, off, cur, N);
        scatter_kernel<<<(E + 255) / 256, 256>>>(srcs[g], dsts[g], ets[g], cur, cgidx, csrc, E, N);

        // initial features -> fp16
        cvt_kernel<<<(N * DIM + 255) / 256, 256>>>(feat[g], h16, N * DIM);

        const float* hcur = feat[g];
        for (int s = 0; s < NSTEPS; s++) {
            // t[k] = h @ W_et[k]^T + b_et[k]   (batched over etypes via z)
            hgemm<<<dim3(1, mblocks, NET), 256>>>(h16, wet16, b_et, t,
                                                  N, DIM, DIM * DIM, N * DIM, DIM);
            // a = segment_sum(t[etype,src], dst)  -> fp16
            agg_kernel<<<N, DIM>>>(off, cgidx, t, a16);
            // gi = a @ W_ih^T + b_ih ; gh = h @ W_hh^T + b_hh
            hgemm<<<dim3(3, mblocks, 1), 256>>>(a16, wih16, b_ih, gi, N, 3 * DIM, 0, 0, 0);
            hgemm<<<dim3(3, mblocks, 1), 256>>>(h16, whh16, b_hh, gh, N, 3 * DIM, 0, 0, 0);
            gru_kernel<<<(N * DIM + 255) / 256, 256>>>(gi, gh, hcur, h, h16, N);
            hcur = h;
        }

        normsig_kernel<<<N, DIM>>>(h, h16);

        // GAT: z = h @ W_fc^T
        hgemm<<<dim3(2, mblocks, 1), 256>>>(h16, wfc16, nullptr, z, N, 2 * DIM, 0, 0, 0);
        eler_kernel<<<N, 256>>>(z, attn_l, attn_r, el, er);
        gat_kernel<<<N, 256>>>(off, csrc, el, er, z, g_bias, gat);

        // pool + classify
        pool_kernel<<<NGR, 256>>>(gids[g], gat, hg, N);
        cls_kernel<<<NGR, 64>>>(hg, W_cls, b_cls, cls + g * NGR * 64);
    }

    final_kernel<<<1, 64>>>(cls, cls + NGR * 64, (float*)d_out);
}

// round 15
// speedup vs baseline: 1.8665x; 1.0402x over previous
#include <cuda_runtime.h>
#include <cuda_fp16.h>
#include <math.h>
#include <stdint.h>

// ---------------- problem constants ----------------
#define NNODES 50000
#define NEDGES 600000
#define DIM    128
#define NET    4
#define NSTEPS 5
#define NGR    64

// ---------------- scratch (device globals; no allocation allowed) ----------------
__device__ __align__(128) float g_h[NNODES * DIM];
__device__ __align__(128) float g_z[NNODES * 2 * DIM];
__device__ __align__(128) float g_gat[NNODES * 2 * DIM];
__device__ float g_el[NNODES * 2];
__device__ float g_er[NNODES * 2];
__device__ int   g_deg[NNODES];
__device__ int   g_off[NNODES + 1];
__device__ int   g_cur[NNODES + 1];
__device__ int   g_csrc[NEDGES];                 // src, dst-sorted
__device__ int   g_cety[NEDGES];                 // etype, dst-sorted
__device__ float g_hg[NGR * 2 * DIM];
__device__ float g_cls[2 * NGR * 64];
__device__ __align__(16) float g_cntf[NNODES * 4];

// fp16 buffers
__device__ __align__(128) __half g_a4[NNODES * 512];       // per-etype aggregated h
__device__ __align__(128) __half g_a16[NNODES * DIM];      // 'a'
__device__ __align__(128) __half g_h16[NNODES * DIM];      // hidden state
__device__ __align__(128) __half g_gi16[NNODES * 3 * DIM];
__device__ __align__(128) __half g_gh16[NNODES * 3 * DIM];
__device__ __align__(128) __half g_bcat16[DIM * 512];      // W_et concat over K
__device__ __align__(128) __half g_wih16[384 * DIM];
__device__ __align__(128) __half g_whh16[384 * DIM];
__device__ __align__(128) __half g_wfc16[256 * DIM];

// =====================================================================
// fp16 tensor-core GEMM (single pass, fp32 accumulate), runtime K:
//   C[m,c] = sum_k A[m,k]*B[c,k] (+ bias / cnt-weighted b_et)
// A [M,K] f16 row-major, B [Ncols,K] f16 row-major.
// Block tile 128x128, 8 warps of 64x32, BK=32, cp.async + ldmatrix.
// Epilogues: Cf!=null -> fp32(+bias); cnt!=null -> fp16 + cnt*b_et;
//            else fp16(+bias).  blockIdx.z==1 selects twin param set.
// =====================================================================
#define LDK  40                    // padded f16 row: 80B, conflict-free LDSM
#define TILEH (128 * LDK)

__device__ __forceinline__ void mma16816(float* c, const unsigned* a, const unsigned* b) {
    asm volatile(
        "mma.sync.aligned.m16n8k16.row.col.f32.f16.f16.f32 "
        "{%0,%1,%2,%3},{%4,%5,%6,%7},{%8,%9},{%0,%1,%2,%3};"
        : "+f"(c[0]), "+f"(c[1]), "+f"(c[2]), "+f"(c[3])
        : "r"(a[0]), "r"(a[1]), "r"(a[2]), "r"(a[3]), "r"(b[0]), "r"(b[1]));
}
__device__ __forceinline__ void ldmx4(unsigned* r, unsigned addr) {
    asm volatile("ldmatrix.sync.aligned.m8n8.x4.shared.b16 {%0,%1,%2,%3}, [%4];"
                 : "=r"(r[0]), "=r"(r[1]), "=r"(r[2]), "=r"(r[3]) : "r"(addr));
}
__device__ __forceinline__ void ldmx2(unsigned* r, unsigned addr) {
    asm volatile("ldmatrix.sync.aligned.m8n8.x2.shared.b16 {%0,%1}, [%2];"
                 : "=r"(r[0]), "=r"(r[1]) : "r"(addr));
}
__device__ __forceinline__ void cpasync16(unsigned dst, const void* src, int sz) {
    asm volatile("cp.async.cg.shared.global [%0], [%1], 16, %2;"
                 :: "r"(dst), "l"(src), "r"(sz));
}

__global__ __launch_bounds__(256) void hgemm2(
    const __half* __restrict__ A, const __half* __restrict__ B,
    const __half* __restrict__ A2, const __half* __restrict__ B2,
    int M, int Ncols, int K,
    const float* __restrict__ bias, const float* __restrict__ bias2,
    const float* __restrict__ cnt, const float* __restrict__ bet,
    float* __restrict__ Cf, __half* __restrict__ Ch, __half* __restrict__ Ch2)
{
    __shared__ __align__(16) __half S[2][128][LDK];   // A, B tiles

    if (blockIdx.z == 1) { A = A2; B = B2; bias = bias2; Ch = Ch2; }

    const int tid = threadIdx.x;
    const int rowBase = blockIdx.y * 128, colBase = blockIdx.x * 128;
    const unsigned sbase = (unsigned)__cvta_generic_to_shared(&S[0][0][0]);

    const int lane = tid & 31, warp = tid >> 5;
    const int warpRow = (warp >> 2) * 64, warpCol = (warp & 3) * 32;
    const unsigned aoff = (unsigned)(((warpRow + (lane & 15)) * LDK + (lane >> 4) * 8) * 2);
    const unsigned boff = (unsigned)(((warpCol + (lane & 7)) * LDK + ((lane >> 3) & 1) * 8) * 2);

    float acc[4][4][4];
#pragma unroll
    for (int i = 0; i < 4; i++)
#pragma unroll
        for (int j = 0; j < 4; j++)
#pragma unroll
            for (int q = 0; q < 4; q++) acc[i][j][q] = 0.f;

    for (int kk = 0; kk < K; kk += 32) {
        // ---- stage: 1024 x 16B chunks (A + B), 4 per thread ----
#pragma unroll
        for (int i = 0; i < 4; i++) {
            int flat = i * 256 + tid;           // 0..1023
            int ab = flat >> 9;                 // 0 = A, 1 = B
            int rem = flat & 511;
            int row = rem >> 2, ch = rem & 3;   // row 0..127, chunk 0..3
            unsigned dst = sbase + (unsigned)(ab * TILEH + row * LDK + ch * 8) * 2u;
            const __half* src;
            int ok = 1;
            if (ab == 0) {
                int gr = rowBase + row;
                ok = (gr < M); if (!ok) gr = 0;
                src = A + (size_t)gr * K + kk + ch * 8;
            } else {
                int gc = colBase + row;         // Ncols always a multiple of 128
                src = B + (size_t)gc * K + kk + ch * 8;
            }
            cpasync16(dst, src, ok ? 16 : 0);
        }
        asm volatile("cp.async.commit_group;");
        asm volatile("cp.async.wait_group 0;");
        __syncthreads();

        const unsigned aB = sbase;
        const unsigned bB = sbase + (unsigned)TILEH * 2u;
#pragma unroll
        for (int ks = 0; ks < 2; ks++) {
            unsigned kb = ks * 32;              // 16 f16 = 32B
            unsigned af[4][4], bf[4][2];
#pragma unroll
            for (int i = 0; i < 4; i++) ldmx4(af[i], aB + aoff + kb + i * 16 * LDK * 2);
#pragma unroll
            for (int j = 0; j < 4; j++) ldmx2(bf[j], bB + boff + kb + j * 8 * LDK * 2);
#pragma unroll
            for (int i = 0; i < 4; i++)
#pragma unroll
                for (int j = 0; j < 4; j++) mma16816(acc[i][j], af[i], bf[j]);
        }
        __syncthreads();
    }

    // ---- epilogue ----
    const int rr = lane >> 2, cc = (lane & 3) * 2;
    if (Cf) {
#pragma unroll
        for (int i = 0; i < 4; i++) {
            int gr0 = rowBase + warpRow + i * 16 + rr;
#pragma unroll
            for (int j = 0; j < 4; j++) {
                int gc = colBase + warpCol + j * 8 + cc;
                float b0 = bias ? bias[gc] : 0.f;
                float b1 = bias ? bias[gc + 1] : 0.f;
                if (gr0 < M) {
                    Cf[(size_t)gr0 * Ncols + gc]     = acc[i][j][0] + b0;
                    Cf[(size_t)gr0 * Ncols + gc + 1] = acc[i][j][1] + b1;
                }
                if (gr0 + 8 < M) {
                    Cf[(size_t)(gr0 + 8) * Ncols + gc]     = acc[i][j][2] + b0;
                    Cf[(size_t)(gr0 + 8) * Ncols + gc + 1] = acc[i][j][3] + b1;
                }
            }
        }
    } else if (cnt) {
#pragma unroll
        for (int i = 0; i < 4; i++) {
            int gr0 = rowBase + warpRow + i * 16 + rr;
            float4 c0 = make_float4(0, 0, 0, 0), c8 = make_float4(0, 0, 0, 0);
            if (gr0 < M)     c0 = *reinterpret_cast<const float4*>(cnt + (size_t)gr0 * 4);
            if (gr0 + 8 < M) c8 = *reinterpret_cast<const float4*>(cnt + (size_t)(gr0 + 8) * 4);
#pragma unroll
            for (int j = 0; j < 4; j++) {
                int gc = colBase + warpCol + j * 8 + cc;
#pragma unroll
                for (int q = 0; q < 2; q++) {
                    float be0 = c0.x * bet[gc + q] + c0.y * bet[128 + gc + q]
                              + c0.z * bet[256 + gc + q] + c0.w * bet[384 + gc + q];
                    float be8 = c8.x * bet[gc + q] + c8.y * bet[128 + gc + q]
                              + c8.z * bet[256 + gc + q] + c8.w * bet[384 + gc + q];
                    if (gr0 < M)
                        Ch[(size_t)gr0 * Ncols + gc + q] = __float2half(acc[i][j][q] + be0);
                    if (gr0 + 8 < M)
                        Ch[(size_t)(gr0 + 8) * Ncols + gc + q] = __float2half(acc[i][j][2 + q] + be8);
                }
            }
        }
    } else {
#pragma unroll
        for (int i = 0; i < 4; i++) {
            int gr0 = rowBase + warpRow + i * 16 + rr;
#pragma unroll
            for (int j = 0; j < 4; j++) {
                int gc = colBase + warpCol + j * 8 + cc;
                float b0 = bias ? bias[gc] : 0.f;
                float b1 = bias ? bias[gc + 1] : 0.f;
                if (gr0 < M) {
                    __half2 hp; hp.x = __float2half(acc[i][j][0] + b0);
                    hp.y = __float2half(acc[i][j][1] + b1);
                    *reinterpret_cast<__half2*>(&Ch[(size_t)gr0 * Ncols + gc]) = hp;
                }
                if (gr0 + 8 < M) {
                    __half2 hp; hp.x = __float2half(acc[i][j][2] + b0);
                    hp.y = __float2half(acc[i][j][3] + b1);
                    *reinterpret_cast<__half2*>(&Ch[(size_t)(gr0 + 8) * Ncols + gc]) = hp;
                }
            }
        }
    }
}

// ---------------- converts ----------------
__global__ void cvt_kernel(const float* __restrict__ s, __half* __restrict__ d, int n) {
    int i = blockIdx.x * blockDim.x + threadIdx.x;
    if (i < n) d[i] = __float2half(s[i]);
}
// Bcat[d][k*128+e] = W_et[k][d][e]
__global__ void bcat_kernel(const float* __restrict__ wet, __half* __restrict__ o) {
    int i = blockIdx.x * blockDim.x + threadIdx.x;
    if (i < 128 * 512) {
        int d = i >> 9, col = i & 511, k = col >> 7, e = col & 127;
        o[i] = __float2half(wet[(k << 14) + (d << 7) + e]);
    }
}

// ---------------- CSR construction ----------------
__global__ void zero_int_kernel(int* p, int n) {
    int i = blockIdx.x * blockDim.x + threadIdx.x;
    if (i < n) p[i] = 0;
}
__global__ void hist_kernel(const int* __restrict__ dst, int* deg, int E) {
    int i = blockIdx.x * blockDim.x + threadIdx.x;
    if (i < E) atomicAdd(&deg[dst[i]], 1);
}
__global__ void scan_kernel(const int* __restrict__ deg, int* off, int* cur, int n) {
    __shared__ int tmp[1024];
    __shared__ int carry_s;
    int t = threadIdx.x;
    if (t == 0) { off[0] = 0; cur[0] = 0; carry_s = 0; }
    __syncthreads();
    for (int base = 0; base < n; base += 1024) {
        int v = (base + t < n) ? deg[base + t] : 0;
        tmp[t] = v;
        __syncthreads();
        for (int s = 1; s < 1024; s <<= 1) {
            int x = (t >= s) ? tmp[t - s] : 0;
            __syncthreads();
            tmp[t] += x;
            __syncthreads();
        }
        int incl = tmp[t] + carry_s;
        if (base + t < n) { off[base + t + 1] = incl; cur[base + t + 1] = incl; }
        __syncthreads();
        if (t == 1023) carry_s = incl;
        __syncthreads();
    }
}
__global__ void scatter_kernel(const int* __restrict__ src, const int* __restrict__ dst,
                               const int* __restrict__ et, int* cur,
                               int* csrc, int* cety, int E) {
    int i = blockIdx.x * blockDim.x + threadIdx.x;
    if (i >= E) return;
    int d = dst[i];
    int p = atomicAdd(&cur[d], 1);
    csrc[p] = src[i];
    cety[p] = et[i];
}

// ---------------- per-etype aggregation of h16 + counts ----------------
__global__ void agg4_kernel(const int* __restrict__ off, const int* __restrict__ csrc,
                            const int* __restrict__ cety, const __half* __restrict__ h16,
                            __half* __restrict__ a4, float* __restrict__ cntf) {
    int n = blockIdx.x, tid = threadIdx.x;   // 128 threads = feature dim
    int s0 = off[n], s1 = off[n + 1];
    __shared__ int sbuf[128], kbuf[128];
    float a0 = 0.f, a1 = 0.f, a2 = 0.f, a3 = 0.f;
    int c0 = 0, c1 = 0, c2 = 0, c3 = 0;
    for (int base = s0; base < s1; base += 128) {
        int cnt = min(128, s1 - base);
        if (tid < cnt) { sbuf[tid] = csrc[base + tid]; kbuf[tid] = cety[base + tid]; }
        __syncthreads();
        for (int i = 0; i < cnt; i++) {
            float v = __half2float(__ldg(&h16[(size_t)sbuf[i] * DIM + tid]));
            int k = kbuf[i];
            if (k == 0)      { a0 += v; c0++; }
            else if (k == 1) { a1 += v; c1++; }
            else if (k == 2) { a2 += v; c2++; }
            else             { a3 += v; c3++; }
        }
        __syncthreads();
    }
    size_t b = (size_t)n * 512 + tid;
    a4[b]       = __float2half(a0);
    a4[b + 128] = __float2half(a1);
    a4[b + 256] = __float2half(a2);
    a4[b + 384] = __float2half(a3);
    if (tid < 4) {
        int cv = (tid == 0) ? c0 : (tid == 1) ? c1 : (tid == 2) ? c2 : c3;
        cntf[n * 4 + tid] = (float)cv;
    }
}

// ---------------- GRU elementwise (fp16 gates, fp32 state, fp16 h out) ----------------
__global__ void gru_kernel(const __half* __restrict__ gi, const __half* __restrict__ gh,
                           const float* __restrict__ hold, float* __restrict__ hnew,
                           __half* __restrict__ h16, int n) {
    int idx = blockIdx.x * blockDim.x + threadIdx.x;
    if (idx >= n * DIM) return;
    int node = idx >> 7, d = idx & 127;
    const __half* gip = gi + (size_t)node * 384;
    const __half* ghp = gh + (size_t)node * 384;
    float r  = 1.f / (1.f + expf(-(__half2float(gip[d]) + __half2float(ghp[d]))));
    float zq = 1.f / (1.f + expf(-(__half2float(gip[128 + d]) + __half2float(ghp[128 + d]))));
    float nn = tanhf(__half2float(gip[256 + d]) + r * __half2float(ghp[256 + d]));
    float h0 = hold[idx];
    float hv = (1.f - zq) * nn + zq * h0;
    hnew[idx] = hv;
    h16[idx] = __float2half(hv);
}

// ---------------- L2 normalize + sigmoid -> fp16 ----------------
__global__ void normsig_kernel(const float* __restrict__ h, __half* __restrict__ h16) {
    int n = blockIdx.x, tid = threadIdx.x;  // 128
    __shared__ float red[128];
    float v = h[(size_t)n * DIM + tid];
    red[tid] = v * v;
    __syncthreads();
    for (int s = 64; s; s >>= 1) {
        if (tid < s) red[tid] += red[tid + s];
        __syncthreads();
    }
    float norm = fmaxf(sqrtf(red[0]), 1e-12f);
    float x = 1.f / (1.f + expf(-(v / norm)));
    h16[(size_t)n * DIM + tid] = __float2half(x);
}

// ---------------- GAT: el/er per node ----------------
__global__ void eler_kernel(const float* __restrict__ z, const float* __restrict__ al,
                            const float* __restrict__ ar, float* __restrict__ el,
                            float* __restrict__ er) {
    int n = blockIdx.x, tid = threadIdx.x;  // 256 = (head, d)
    __shared__ float sl[256], sr[256];
    float zv = z[(size_t)n * 256 + tid];
    sl[tid] = zv * al[tid];
    sr[tid] = zv * ar[tid];
    __syncthreads();
    int lane = tid & 127;
    for (int s = 64; s; s >>= 1) {
        if (lane < s) { sl[tid] += sl[tid + s]; sr[tid] += sr[tid + s]; }
        __syncthreads();
    }
    if (lane == 0) {
        int h = tid >> 7;
        el[n * 2 + h] = sl[tid];
        er[n * 2 + h] = sr[tid];
    }
}

// ---------------- GAT: edge softmax + weighted aggregation ----------------
__global__ void gat_kernel(const int* __restrict__ off, const int* __restrict__ csrc,
                           const float* __restrict__ el, const float* __restrict__ er,
                           const float* __restrict__ z, const float* __restrict__ bias,
                           float* __restrict__ outp) {
    int n = blockIdx.x, tid = threadIdx.x;  // 256 = (head, d)
    int h = tid >> 7, lane = tid & 127;
    int s0 = off[n], s1 = off[n + 1];
    float er_nh = er[n * 2 + h];

    __shared__ float red[256];
    __shared__ float mden[4];
    __shared__ float wbuf[2][128];
    __shared__ int   sbuf[128];

    float lmax = -3.0e38f;
    for (int e = s0 + lane; e < s1; e += 128) {
        float x = el[csrc[e] * 2 + h] + er_nh;
        x = x > 0.f ? x : 0.2f * x;
        lmax = fmaxf(lmax, x);
    }
    red[tid] = lmax;
    __syncthreads();
    for (int s = 64; s; s >>= 1) {
        if (lane < s) red[tid] = fmaxf(red[tid], red[tid + s]);
        __syncthreads();
    }
    if (lane == 0) mden[h] = red[tid];
    __syncthreads();
    float m = mden[h];

    float lsum = 0.f;
    for (int e = s0 + lane; e < s1; e += 128) {
        float x = el[csrc[e] * 2 + h] + er_nh;
        x = x > 0.f ? x : 0.2f * x;
        lsum += expf(x - m);
    }
    red[tid] = lsum;
    __syncthreads();
    for (int s = 64; s; s >>= 1) {
        if (lane < s) red[tid] += red[tid + s];
        __syncthreads();
    }
    if (lane == 0) mden[2 + h] = 1.f / red[tid];
    __syncthreads();
    float invden = mden[2 + h];

    float acc = 0.f;
    for (int base = s0; base < s1; base += 128) {
        int cnt = min(128, s1 - base);
        if (lane < cnt) {
            int sn = csrc[base + lane];
            float x = el[sn * 2 + h] + er_nh;
            x = x > 0.f ? x : 0.2f * x;
            wbuf[h][lane] = expf(x - m) * invden;
            if (h == 0) sbuf[lane] = sn;
        }
        __syncthreads();
        for (int i = 0; i < cnt; i++)
            acc = fmaf(wbuf[h][i], z[(size_t)sbuf[i] * 256 + tid], acc);
        __syncthreads();
    }
    float o = acc + bias[tid];
    outp[(size_t)n * 256 + tid] = fmaxf(o, 0.f);
}

// ---------------- graph mean-pool ----------------
__global__ void pool_kernel(const int* __restrict__ gid, const float* __restrict__ hgat,
                            float* __restrict__ hg, int n) {
    int b = blockIdx.x, tid = threadIdx.x;  // 256
    __shared__ int s_lo, s_hi;
    if (tid == 0) {
        int lo = 0, hi = n;
        while (lo < hi) { int mid = (lo + hi) >> 1; if (gid[mid] < b) lo = mid + 1; else hi = mid; }
        s_lo = lo;
        lo = 0; hi = n;
        while (lo < hi) { int mid = (lo + hi) >> 1; if (gid[mid] < b + 1) lo = mid + 1; else hi = mid; }
        s_hi = lo;
    }
    __syncthreads();
    float acc = 0.f;
    for (int node = s_lo; node < s_hi; node++)
        acc += hgat[(size_t)node * 256 + tid];
    float cnt = (float)(s_hi - s_lo);
    hg[b * 256 + tid] = acc / fmaxf(cnt, 1.f);
}

// ---------------- classifier ----------------
__global__ void cls_kernel(const float* __restrict__ hg, const float* __restrict__ Wc,
                           const float* __restrict__ bc, float* __restrict__ outc) {
    int b = blockIdx.x, tid = threadIdx.x;  // 64 = (head, c)
    __shared__ float sh[256];
    for (int i = tid; i < 256; i += 64) sh[i] = hg[b * 256 + i];
    __syncthreads();
    int h = tid >> 5, c = tid & 31;
    float s = bc[c];
    for (int d = 0; d < DIM; d++)
        s = fmaf(sh[h * 128 + d], Wc[c * 128 + d], s);
    outc[b * 64 + tid] = s;
}

// ---------------- pairwise distance + softmax over heads ----------------
__global__ void final_kernel(const float* __restrict__ c1, const float* __restrict__ c2,
                             float* __restrict__ out) {
    int b = threadIdx.x;
    if (b >= NGR) return;
    float dist[2];
    for (int h = 0; h < 2; h++) {
        float ss = 0.f;
        for (int c = 0; c < 32; c++) {
            float diff = c1[b * 64 + h * 32 + c] - c2[b * 64 + h * 32 + c] + 1e-6f;
            ss += diff * diff;
        }
        dist[h] = sqrtf(ss);
    }
    float mx = fmaxf(dist[0], dist[1]);
    float e0 = expf(dist[0] - mx), e1 = expf(dist[1] - mx);
    float inv = 1.f / (e0 + e1);
    out[b * 2 + 0] = e0 * inv;
    out[b * 2 + 1] = e1 * inv;
}

// ---------------- host launcher ----------------
extern "C" void kernel_launch(void* const* d_in, const int* in_sizes, int n_in,
                              void* d_out, int out_size) {
    const float* feat[2] = {(const float*)d_in[0], (const float*)d_in[1]};
    const int* srcs[2] = {(const int*)d_in[2], (const int*)d_in[6]};
    const int* dsts[2] = {(const int*)d_in[3], (const int*)d_in[7]};
    const int* ets[2]  = {(const int*)d_in[4], (const int*)d_in[8]};
    const int* gids[2] = {(const int*)d_in[5], (const int*)d_in[9]};
    const float* W_et   = (const float*)d_in[10];
    const float* b_et   = (const float*)d_in[11];
    const float* W_ih   = (const float*)d_in[12];
    const float* W_hh   = (const float*)d_in[13];
    const float* b_ih   = (const float*)d_in[14];
    const float* b_hh   = (const float*)d_in[15];
    const float* W_fc   = (const float*)d_in[16];
    const float* attn_l = (const float*)d_in[17];
    const float* attn_r = (const float*)d_in[18];
    const float* g_bias = (const float*)d_in[19];
    const float* W_cls  = (const float*)d_in[20];
    const float* b_cls  = (const float*)d_in[21];

    int N = in_sizes[0] / DIM;
    int E = in_sizes[2];

    float *h, *z, *gat, *el, *er, *hg, *cls, *cntf;
    int *deg, *off, *cur, *csrc, *cety;
    __half *a4, *a16, *h16, *gi16, *gh16, *bcat16, *wih16, *whh16, *wfc16;
    cudaGetSymbolAddress((void**)&h, g_h);
    cudaGetSymbolAddress((void**)&z, g_z);
    cudaGetSymbolAddress((void**)&gat, g_gat);
    cudaGetSymbolAddress((void**)&el, g_el);
    cudaGetSymbolAddress((void**)&er, g_er);
    cudaGetSymbolAddress((void**)&deg, g_deg);
    cudaGetSymbolAddress((void**)&off, g_off);
    cudaGetSymbolAddress((void**)&cur, g_cur);
    cudaGetSymbolAddress((void**)&csrc, g_csrc);
    cudaGetSymbolAddress((void**)&cety, g_cety);
    cudaGetSymbolAddress((void**)&hg, g_hg);
    cudaGetSymbolAddress((void**)&cls, g_cls);
    cudaGetSymbolAddress((void**)&cntf, g_cntf);
    cudaGetSymbolAddress((void**)&a4, g_a4);
    cudaGetSymbolAddress((void**)&a16, g_a16);
    cudaGetSymbolAddress((void**)&h16, g_h16);
    cudaGetSymbolAddress((void**)&gi16, g_gi16);
    cudaGetSymbolAddress((void**)&gh16, g_gh16);
    cudaGetSymbolAddress((void**)&bcat16, g_bcat16);
    cudaGetSymbolAddress((void**)&wih16, g_wih16);
    cudaGetSymbolAddress((void**)&whh16, g_whh16);
    cudaGetSymbolAddress((void**)&wfc16, g_wfc16);

    // convert weights (once per launch; tiny)
    bcat_kernel<<<(128 * 512 + 255) / 256, 256>>>(W_et, bcat16);
    cvt_kernel<<<(384 * 128 + 255) / 256, 256>>>(W_ih, wih16, 384 * 128);
    cvt_kernel<<<(384 * 128 + 255) / 256, 256>>>(W_hh, whh16, 384 * 128);
    cvt_kernel<<<(256 * 128 + 255) / 256, 256>>>(W_fc, wfc16, 256 * 128);

    int mblocks = (N + 127) / 128;

    for (int g = 0; g < 2; g++) {
        // CSR by dst
        zero_int_kernel<<<(N + 255) / 256, 256>>>(deg, N);
        hist_kernel<<<(E + 255) / 256, 256>>>(dsts[g], deg, E);
        scan_kernel<<<1, 1024>>>(deg, off, cur, N);
        scatter_kernel<<<(E + 255) / 256, 256>>>(srcs[g], dsts[g], ets[g], cur, csrc, cety, E);

        // initial features -> fp16
        cvt_kernel<<<(N * DIM + 255) / 256, 256>>>(feat[g], h16, N * DIM);

        const float* hcur = feat[g];
        for (int s = 0; s < NSTEPS; s++) {
            // per-etype aggregation of h -> A4 + counts
            agg4_kernel<<<N, DIM>>>(off, csrc, cety, h16, a4, cntf);
            // a = A4 @ Bcat^T + cnt-weighted b_et   (K=512, fp16 out)
            hgemm2<<<dim3(1, mblocks, 1), 256>>>(
                a4, bcat16, nullptr, nullptr, N, 128, 512,
                nullptr, nullptr, cntf, b_et, nullptr, a16, nullptr);
            // twin: gi = a @ W_ih^T + b_ih ; gh = h @ W_hh^T + b_hh  (fp16 out)
            hgemm2<<<dim3(3, mblocks, 2), 256>>>(
                a16, wih16, h16, whh16, N, 384, 128,
                b_ih, b_hh, nullptr, nullptr, nullptr, gi16, gh16);
            gru_kernel<<<(N * DIM + 255) / 256, 256>>>(gi16, gh16, hcur, h, h16, N);
            hcur = h;
        }

        normsig_kernel<<<N, DIM>>>(h, h16);

        // GAT: z = h @ W_fc^T  (fp32 out)
        hgemm2<<<dim3(2, mblocks, 1), 256>>>(
            h16, wfc16, nullptr, nullptr, N, 256, 128,
            nullptr, nullptr, nullptr, nullptr, z, nullptr, nullptr);
        eler_kernel<<<N, 256>>>(z, attn_l, attn_r, el, er);
        gat_kernel<<<N, 256>>>(off, csrc, el, er, z, g_bias, gat);

        // pool + classify
        pool_kernel<<<NGR, 256>>>(gids[g], gat, hg, N);
        cls_kernel<<<NGR, 64>>>(hg, W_cls, b_cls, cls + g * NGR * 64);
    }

    final_kernel<<<1, 64>>>(cls, cls + NGR * 64, (float*)d_out);
}

// round 16
// speedup vs baseline: 2.0949x; 1.1224x over previous
#include <cuda_runtime.h>
#include <cuda_fp16.h>
#include <math.h>
#include <stdint.h>

// ---------------- problem constants ----------------
#define NNODES 50000
#define NEDGES 600000
#define DIM    128
#define NET    4
#define NSTEPS 5
#define NGR    64

// ---------------- scratch (device globals; no allocation allowed) ----------------
__device__ __align__(128) float g_h[NNODES * DIM];
__device__ __align__(128) float g_z[NNODES * 2 * DIM];
__device__ __align__(128) float g_gat[NNODES * 2 * DIM];
__device__ float g_el[NNODES * 2];
__device__ float g_er[NNODES * 2];
__device__ int   g_deg[NNODES];
__device__ int   g_off[NNODES + 1];
__device__ int   g_cur[NNODES + 1];
__device__ int   g_csrc[NEDGES];                 // src, dst-sorted
__device__ int   g_cety[NEDGES];                 // etype, dst-sorted
__device__ float g_hg[NGR * 2 * DIM];
__device__ float g_cls[2 * NGR * 64];
__device__ __align__(16) float g_cntf[NNODES * 4];

// fp16 buffers
__device__ __align__(128) __half g_a4[NNODES * 512];       // per-etype aggregated h
__device__ __align__(128) __half g_a16[NNODES * DIM];      // 'a'
__device__ __align__(128) __half g_h16[NNODES * DIM];      // hidden state
__device__ __align__(128) __half g_gi16[NNODES * 3 * DIM];
__device__ __align__(128) __half g_gh16[NNODES * 3 * DIM];
__device__ __align__(128) __half g_bcat16[DIM * 512];      // W_et concat over K
__device__ __align__(128) __half g_wih16[384 * DIM];
__device__ __align__(128) __half g_whh16[384 * DIM];
__device__ __align__(128) __half g_wfc16[256 * DIM];

// =====================================================================
// fp16 tensor-core GEMM, double-buffered cp.async pipeline, runtime K:
//   C[m,c] = sum_k A[m,k]*B[c,k] (+ bias / cnt-weighted b_et)
// Block tile 128x128, 8 warps of 64x32, BK=32, ldmatrix fragments.
// Epilogues: Cf!=null -> fp32(+bias); cnt!=null -> fp16 + cnt*b_et;
//            else fp16(+bias).  blockIdx.z==1 selects twin param set.
// =====================================================================
#define LDK  40                    // padded f16 row: 80B, conflict-free LDSM
#define TILEH (128 * LDK)

__device__ __forceinline__ void mma16816(float* c, const unsigned* a, const unsigned* b) {
    asm volatile(
        "mma.sync.aligned.m16n8k16.row.col.f32.f16.f16.f32 "
        "{%0,%1,%2,%3},{%4,%5,%6,%7},{%8,%9},{%0,%1,%2,%3};"
        : "+f"(c[0]), "+f"(c[1]), "+f"(c[2]), "+f"(c[3])
        : "r"(a[0]), "r"(a[1]), "r"(a[2]), "r"(a[3]), "r"(b[0]), "r"(b[1]));
}
__device__ __forceinline__ void ldmx4(unsigned* r, unsigned addr) {
    asm volatile("ldmatrix.sync.aligned.m8n8.x4.shared.b16 {%0,%1,%2,%3}, [%4];"
                 : "=r"(r[0]), "=r"(r[1]), "=r"(r[2]), "=r"(r[3]) : "r"(addr));
}
__device__ __forceinline__ void ldmx2(unsigned* r, unsigned addr) {
    asm volatile("ldmatrix.sync.aligned.m8n8.x2.shared.b16 {%0,%1}, [%2];"
                 : "=r"(r[0]), "=r"(r[1]) : "r"(addr));
}
__device__ __forceinline__ void cpasync16(unsigned dst, const void* src, int sz) {
    asm volatile("cp.async.cg.shared.global [%0], [%1], 16, %2;"
                 :: "r"(dst), "l"(src), "r"(sz));
}

__global__ __launch_bounds__(256) void hgemm2(
    const __half* __restrict__ A, const __half* __restrict__ B,
    const __half* __restrict__ A2, const __half* __restrict__ B2,
    int M, int Ncols, int K,
    const float* __restrict__ bias, const float* __restrict__ bias2,
    const float* __restrict__ cnt, const float* __restrict__ bet,
    float* __restrict__ Cf, __half* __restrict__ Ch, __half* __restrict__ Ch2)
{
    __shared__ __align__(16) __half S[2][2][128][LDK];   // [buf][A/B]

    if (blockIdx.z == 1) { A = A2; B = B2; bias = bias2; Ch = Ch2; }

    const int tid = threadIdx.x;
    const int rowBase = blockIdx.y * 128, colBase = blockIdx.x * 128;
    const unsigned sbase = (unsigned)__cvta_generic_to_shared(&S[0][0][0][0]);

    const int lane = tid & 31, warp = tid >> 5;
    const int warpRow = (warp >> 2) * 64, warpCol = (warp & 3) * 32;
    const unsigned aoff = (unsigned)(((warpRow + (lane & 15)) * LDK + (lane >> 4) * 8) * 2);
    const unsigned boff = (unsigned)(((warpCol + (lane & 7)) * LDK + ((lane >> 3) & 1) * 8) * 2);

    auto stage = [&](int buf, int kk) {
#pragma unroll
        for (int i = 0; i < 4; i++) {
            int flat = i * 256 + tid;           // 0..1023
            int ab = flat >> 9;                 // 0 = A, 1 = B
            int rem = flat & 511;
            int row = rem >> 2, ch = rem & 3;   // row 0..127, chunk 0..3
            unsigned dst = sbase + (unsigned)((buf * 2 + ab) * TILEH + row * LDK + ch * 8) * 2u;
            const __half* src;
            int ok = 1;
            if (ab == 0) {
                int gr = rowBase + row;
                ok = (gr < M); if (!ok) gr = 0;
                src = A + (size_t)gr * K + kk + ch * 8;
            } else {
                int gc = colBase + row;         // Ncols always a multiple of 128
                src = B + (size_t)gc * K + kk + ch * 8;
            }
            cpasync16(dst, src, ok ? 16 : 0);
        }
        asm volatile("cp.async.commit_group;");
    };

    float acc[4][4][4];
#pragma unroll
    for (int i = 0; i < 4; i++)
#pragma unroll
        for (int j = 0; j < 4; j++)
#pragma unroll
            for (int q = 0; q < 4; q++) acc[i][j][q] = 0.f;

    stage(0, 0);
    const int nk = K >> 5;
    for (int it = 0; it < nk; it++) {
        int buf = it & 1;
        if (it + 1 < nk) {
            stage(buf ^ 1, (it + 1) * 32);
            asm volatile("cp.async.wait_group 1;");
        } else {
            asm volatile("cp.async.wait_group 0;");
        }
        __syncthreads();
        const unsigned aB = sbase + (unsigned)((buf * 2 + 0) * TILEH) * 2u;
        const unsigned bB = sbase + (unsigned)((buf * 2 + 1) * TILEH) * 2u;
#pragma unroll
        for (int ks = 0; ks < 2; ks++) {
            unsigned kb = ks * 32;              // 16 f16 = 32B
            unsigned af[4][4], bf[4][2];
#pragma unroll
            for (int i = 0; i < 4; i++) ldmx4(af[i], aB + aoff + kb + i * 16 * LDK * 2);
#pragma unroll
            for (int j = 0; j < 4; j++) ldmx2(bf[j], bB + boff + kb + j * 8 * LDK * 2);
#pragma unroll
            for (int i = 0; i < 4; i++)
#pragma unroll
                for (int j = 0; j < 4; j++) mma16816(acc[i][j], af[i], bf[j]);
        }
        __syncthreads();
    }

    // ---- epilogue ----
    const int rr = lane >> 2, cc = (lane & 3) * 2;
    if (Cf) {
#pragma unroll
        for (int i = 0; i < 4; i++) {
            int gr0 = rowBase + warpRow + i * 16 + rr;
#pragma unroll
            for (int j = 0; j < 4; j++) {
                int gc = colBase + warpCol + j * 8 + cc;
                float b0 = bias ? bias[gc] : 0.f;
                float b1 = bias ? bias[gc + 1] : 0.f;
                if (gr0 < M) {
                    Cf[(size_t)gr0 * Ncols + gc]     = acc[i][j][0] + b0;
                    Cf[(size_t)gr0 * Ncols + gc + 1] = acc[i][j][1] + b1;
                }
                if (gr0 + 8 < M) {
                    Cf[(size_t)(gr0 + 8) * Ncols + gc]     = acc[i][j][2] + b0;
                    Cf[(size_t)(gr0 + 8) * Ncols + gc + 1] = acc[i][j][3] + b1;
                }
            }
        }
    } else if (cnt) {
#pragma unroll
        for (int i = 0; i < 4; i++) {
            int gr0 = rowBase + warpRow + i * 16 + rr;
            float4 c0 = make_float4(0, 0, 0, 0), c8 = make_float4(0, 0, 0, 0);
            if (gr0 < M)     c0 = *reinterpret_cast<const float4*>(cnt + (size_t)gr0 * 4);
            if (gr0 + 8 < M) c8 = *reinterpret_cast<const float4*>(cnt + (size_t)(gr0 + 8) * 4);
#pragma unroll
            for (int j = 0; j < 4; j++) {
                int gc = colBase + warpCol + j * 8 + cc;
#pragma unroll
                for (int q = 0; q < 2; q++) {
                    float be0 = c0.x * bet[gc + q] + c0.y * bet[128 + gc + q]
                              + c0.z * bet[256 + gc + q] + c0.w * bet[384 + gc + q];
                    float be8 = c8.x * bet[gc + q] + c8.y * bet[128 + gc + q]
                              + c8.z * bet[256 + gc + q] + c8.w * bet[384 + gc + q];
                    if (gr0 < M)
                        Ch[(size_t)gr0 * Ncols + gc + q] = __float2half(acc[i][j][q] + be0);
                    if (gr0 + 8 < M)
                        Ch[(size_t)(gr0 + 8) * Ncols + gc + q] = __float2half(acc[i][j][2 + q] + be8);
                }
            }
        }
    } else {
#pragma unroll
        for (int i = 0; i < 4; i++) {
            int gr0 = rowBase + warpRow + i * 16 + rr;
#pragma unroll
            for (int j = 0; j < 4; j++) {
                int gc = colBase + warpCol + j * 8 + cc;
                float b0 = bias ? bias[gc] : 0.f;
                float b1 = bias ? bias[gc + 1] : 0.f;
                if (gr0 < M) {
                    __half2 hp; hp.x = __float2half(acc[i][j][0] + b0);
                    hp.y = __float2half(acc[i][j][1] + b1);
                    *reinterpret_cast<__half2*>(&Ch[(size_t)gr0 * Ncols + gc]) = hp;
                }
                if (gr0 + 8 < M) {
                    __half2 hp; hp.x = __float2half(acc[i][j][2] + b0);
                    hp.y = __float2half(acc[i][j][3] + b1);
                    *reinterpret_cast<__half2*>(&Ch[(size_t)(gr0 + 8) * Ncols + gc]) = hp;
                }
            }
        }
    }
}

// ---------------- converts ----------------
__global__ void cvt_kernel(const float* __restrict__ s, __half* __restrict__ d, int n) {
    int i = blockIdx.x * blockDim.x + threadIdx.x;
    if (i < n) d[i] = __float2half(s[i]);
}
// Bcat[d][k*128+e] = W_et[k][d][e]
__global__ void bcat_kernel(const float* __restrict__ wet, __half* __restrict__ o) {
    int i = blockIdx.x * blockDim.x + threadIdx.x;
    if (i < 128 * 512) {
        int d = i >> 9, col = i & 511, k = col >> 7, e = col & 127;
        o[i] = __float2half(wet[(k << 14) + (d << 7) + e]);
    }
}

// ---------------- CSR construction ----------------
__global__ void zero_int_kernel(int* p, int n) {
    int i = blockIdx.x * blockDim.x + threadIdx.x;
    if (i < n) p[i] = 0;
}
__global__ void hist_kernel(const int* __restrict__ dst, int* deg, int E) {
    int i = blockIdx.x * blockDim.x + threadIdx.x;
    if (i < E) atomicAdd(&deg[dst[i]], 1);
}
__global__ void scan_kernel(const int* __restrict__ deg, int* off, int* cur, int n) {
    __shared__ int tmp[1024];
    __shared__ int carry_s;
    int t = threadIdx.x;
    if (t == 0) { off[0] = 0; cur[0] = 0; carry_s = 0; }
    __syncthreads();
    for (int base = 0; base < n; base += 1024) {
        int v = (base + t < n) ? deg[base + t] : 0;
        tmp[t] = v;
        __syncthreads();
        for (int s = 1; s < 1024; s <<= 1) {
            int x = (t >= s) ? tmp[t - s] : 0;
            __syncthreads();
            tmp[t] += x;
            __syncthreads();
        }
        int incl = tmp[t] + carry_s;
        if (base + t < n) { off[base + t + 1] = incl; cur[base + t + 1] = incl; }
        __syncthreads();
        if (t == 1023) carry_s = incl;
        __syncthreads();
    }
}
__global__ void scatter_kernel(const int* __restrict__ src, const int* __restrict__ dst,
                               const int* __restrict__ et, int* cur,
                               int* csrc, int* cety, int E) {
    int i = blockIdx.x * blockDim.x + threadIdx.x;
    if (i >= E) return;
    int d = dst[i];
    int p = atomicAdd(&cur[d], 1);
    csrc[p] = src[i];
    cety[p] = et[i];
}

// ---------------- per-etype aggregation of h16 + counts (MLP-4) ----------------
__global__ void agg4_kernel(const int* __restrict__ off, const int* __restrict__ csrc,
                            const int* __restrict__ cety, const __half* __restrict__ h16,
                            __half* __restrict__ a4, float* __restrict__ cntf) {
    int n = blockIdx.x, tid = threadIdx.x;   // 128 threads = feature dim
    int s0 = off[n], s1 = off[n + 1];
    __shared__ int sbuf[128], kbuf[128];
    float a0 = 0.f, a1 = 0.f, a2 = 0.f, a3 = 0.f;
    int c0 = 0, c1 = 0, c2 = 0, c3 = 0;
    for (int base = s0; base < s1; base += 128) {
        int cnt = min(128, s1 - base);
        if (tid < cnt) { sbuf[tid] = csrc[base + tid]; kbuf[tid] = cety[base + tid]; }
        __syncthreads();
        int i = 0;
        for (; i + 4 <= cnt; i += 4) {
            float v0 = __half2float(__ldg(&h16[(size_t)sbuf[i]     * DIM + tid]));
            float v1 = __half2float(__ldg(&h16[(size_t)sbuf[i + 1] * DIM + tid]));
            float v2 = __half2float(__ldg(&h16[(size_t)sbuf[i + 2] * DIM + tid]));
            float v3 = __half2float(__ldg(&h16[(size_t)sbuf[i + 3] * DIM + tid]));
            int k0 = kbuf[i], k1 = kbuf[i + 1], k2 = kbuf[i + 2], k3 = kbuf[i + 3];
            if (k0 == 0) { a0 += v0; c0++; } else if (k0 == 1) { a1 += v0; c1++; }
            else if (k0 == 2) { a2 += v0; c2++; } else { a3 += v0; c3++; }
            if (k1 == 0) { a0 += v1; c0++; } else if (k1 == 1) { a1 += v1; c1++; }
            else if (k1 == 2) { a2 += v1; c2++; } else { a3 += v1; c3++; }
            if (k2 == 0) { a0 += v2; c0++; } else if (k2 == 1) { a1 += v2; c1++; }
            else if (k2 == 2) { a2 += v2; c2++; } else { a3 += v2; c3++; }
            if (k3 == 0) { a0 += v3; c0++; } else if (k3 == 1) { a1 += v3; c1++; }
            else if (k3 == 2) { a2 += v3; c2++; } else { a3 += v3; c3++; }
        }
        for (; i < cnt; i++) {
            float v = __half2float(__ldg(&h16[(size_t)sbuf[i] * DIM + tid]));
            int k = kbuf[i];
            if (k == 0)      { a0 += v; c0++; }
            else if (k == 1) { a1 += v; c1++; }
            else if (k == 2) { a2 += v; c2++; }
            else             { a3 += v; c3++; }
        }
        __syncthreads();
    }
    size_t b = (size_t)n * 512 + tid;
    a4[b]       = __float2half(a0);
    a4[b + 128] = __float2half(a1);
    a4[b + 256] = __float2half(a2);
    a4[b + 384] = __float2half(a3);
    if (tid < 4) {
        int cv = (tid == 0) ? c0 : (tid == 1) ? c1 : (tid == 2) ? c2 : c3;
        cntf[n * 4 + tid] = (float)cv;
    }
}

// ---------------- GRU elementwise (half2, 2 features/thread) ----------------
__global__ void gru_kernel(const __half2* __restrict__ gi, const __half2* __restrict__ gh,
                           const float2* __restrict__ hold, float2* __restrict__ hnew,
                           __half2* __restrict__ h16, int n) {
    int idx = blockIdx.x * blockDim.x + threadIdx.x;   // over n*64 half2 elems
    if (idx >= n * 64) return;
    int node = idx >> 6, d2 = idx & 63;
    const __half2* gip = gi + (size_t)node * 192;      // 384 halves = 192 half2
    const __half2* ghp = gh + (size_t)node * 192;
    float2 ir = __half22float2(gip[d2]),       hr = __half22float2(ghp[d2]);
    float2 iz = __half22float2(gip[64 + d2]),  hz = __half22float2(ghp[64 + d2]);
    float2 in_ = __half22float2(gip[128 + d2]), hn = __half22float2(ghp[128 + d2]);
    float rx = 1.f / (1.f + expf(-(ir.x + hr.x)));
    float ry = 1.f / (1.f + expf(-(ir.y + hr.y)));
    float zx = 1.f / (1.f + expf(-(iz.x + hz.x)));
    float zy = 1.f / (1.f + expf(-(iz.y + hz.y)));
    float nx = tanhf(in_.x + rx * hn.x);
    float ny = tanhf(in_.y + ry * hn.y);
    float2 h0 = hold[idx];
    float hx = (1.f - zx) * nx + zx * h0.x;
    float hy = (1.f - zy) * ny + zy * h0.y;
    hnew[idx] = make_float2(hx, hy);
    h16[idx] = __floats2half2_rn(hx, hy);
}

// ---------------- L2 normalize + sigmoid -> fp16 ----------------
__global__ void normsig_kernel(const float* __restrict__ h, __half* __restrict__ h16) {
    int n = blockIdx.x, tid = threadIdx.x;  // 128
    __shared__ float red[128];
    float v = h[(size_t)n * DIM + tid];
    red[tid] = v * v;
    __syncthreads();
    for (int s = 64; s; s >>= 1) {
        if (tid < s) red[tid] += red[tid + s];
        __syncthreads();
    }
    float norm = fmaxf(sqrtf(red[0]), 1e-12f);
    float x = 1.f / (1.f + expf(-(v / norm)));
    h16[(size_t)n * DIM + tid] = __float2half(x);
}

// ---------------- GAT: el/er per node ----------------
__global__ void eler_kernel(const float* __restrict__ z, const float* __restrict__ al,
                            const float* __restrict__ ar, float* __restrict__ el,
                            float* __restrict__ er) {
    int n = blockIdx.x, tid = threadIdx.x;  // 256 = (head, d)
    __shared__ float sl[256], sr[256];
    float zv = z[(size_t)n * 256 + tid];
    sl[tid] = zv * al[tid];
    sr[tid] = zv * ar[tid];
    __syncthreads();
    int lane = tid & 127;
    for (int s = 64; s; s >>= 1) {
        if (lane < s) { sl[tid] += sl[tid + s]; sr[tid] += sr[tid + s]; }
        __syncthreads();
    }
    if (lane == 0) {
        int h = tid >> 7;
        el[n * 2 + h] = sl[tid];
        er[n * 2 + h] = sr[tid];
    }
}

// ---------------- GAT: edge softmax + warp-parallel aggregation ----------------
__global__ void gat_kernel(const int* __restrict__ off, const int* __restrict__ csrc,
                           const float* __restrict__ el, const float* __restrict__ er,
                           const float* __restrict__ z, const float* __restrict__ bias,
                           float* __restrict__ outp) {
    int n = blockIdx.x, tid = threadIdx.x;  // 256
    int warp = tid >> 5, lane = tid & 31;
    int h = tid >> 7, lane128 = tid & 127;
    int s0 = off[n], s1 = off[n + 1];
    float er_nh = er[n * 2 + h];

    __shared__ float red[256];
    __shared__ float mden[4];          // m0, m1, inv0, inv1
    __shared__ float part[8][256];

    // pass 1: per-head max
    float lmax = -3.0e38f;
    for (int e = s0 + lane128; e < s1; e += 128) {
        float x = el[csrc[e] * 2 + h] + er_nh;
        x = x > 0.f ? x : 0.2f * x;
        lmax = fmaxf(lmax, x);
    }
    red[tid] = lmax;
    __syncthreads();
    for (int s = 64; s; s >>= 1) {
        if (lane128 < s) red[tid] = fmaxf(red[tid], red[tid + s]);
        __syncthreads();
    }
    if (lane128 == 0) mden[h] = red[tid];
    __syncthreads();
    float m = mden[h];

    // pass 2: denominator
    float lsum = 0.f;
    for (int e = s0 + lane128; e < s1; e += 128) {
        float x = el[csrc[e] * 2 + h] + er_nh;
        x = x > 0.f ? x : 0.2f * x;
        lsum += expf(x - m);
    }
    red[tid] = lsum;
    __syncthreads();
    for (int s = 64; s; s >>= 1) {
        if (lane128 < s) red[tid] += red[tid + s];
        __syncthreads();
    }
    if (lane128 == 0) mden[2 + h] = 1.f / red[tid];
    __syncthreads();

    // pass 3: warp-parallel weighted accumulation (warp w -> edges w, w+8, ...)
    float m0 = mden[0], m1 = mden[1], inv0 = mden[2], inv1 = mden[3];
    float er0 = er[n * 2 + 0], er1 = er[n * 2 + 1];
    float pacc[8];
#pragma unroll
    for (int r = 0; r < 8; r++) pacc[r] = 0.f;
    for (int e = s0 + warp; e < s1; e += 8) {
        int sn = __ldg(&csrc[e]);
        float x0 = __ldg(&el[sn * 2 + 0]) + er0;
        x0 = x0 > 0.f ? x0 : 0.2f * x0;
        float w0 = expf(x0 - m0) * inv0;
        float x1 = __ldg(&el[sn * 2 + 1]) + er1;
        x1 = x1 > 0.f ? x1 : 0.2f * x1;
        float w1 = expf(x1 - m1) * inv1;
        const float* zr = z + (size_t)sn * 256;
#pragma unroll
        for (int r = 0; r < 8; r++) {
            float zv = __ldg(&zr[lane + r * 32]);
            pacc[r] = fmaf((r < 4 ? w0 : w1), zv, pacc[r]);
        }
    }
#pragma unroll
    for (int r = 0; r < 8; r++) part[warp][lane + r * 32] = pacc[r];
    __syncthreads();
    float acc = 0.f;
#pragma unroll
    for (int w = 0; w < 8; w++) acc += part[w][tid];
    outp[(size_t)n * 256 + tid] = fmaxf(acc + bias[tid], 0.f);
}

// ---------------- graph mean-pool ----------------
__global__ void pool_kernel(const int* __restrict__ gid, const float* __restrict__ hgat,
                            float* __restrict__ hg, int n) {
    int b = blockIdx.x, tid = threadIdx.x;  // 256
    __shared__ int s_lo, s_hi;
    if (tid == 0) {
        int lo = 0, hi = n;
        while (lo < hi) { int mid = (lo + hi) >> 1; if (gid[mid] < b) lo = mid + 1; else hi = mid; }
        s_lo = lo;
        lo = 0; hi = n;
        while (lo < hi) { int mid = (lo + hi) >> 1; if (gid[mid] < b + 1) lo = mid + 1; else hi = mid; }
        s_hi = lo;
    }
    __syncthreads();
    float acc = 0.f;
    for (int node = s_lo; node < s_hi; node++)
        acc += hgat[(size_t)node * 256 + tid];
    float cnt = (float)(s_hi - s_lo);
    hg[b * 256 + tid] = acc / fmaxf(cnt, 1.f);
}

// ---------------- classifier ----------------
__global__ void cls_kernel(const float* __restrict__ hg, const float* __restrict__ Wc,
                           const float* __restrict__ bc, float* __restrict__ outc) {
    int b = blockIdx.x, tid = threadIdx.x;  // 64 = (head, c)
    __shared__ float sh[256];
    for (int i = tid; i < 256; i += 64) sh[i] = hg[b * 256 + i];
    __syncthreads();
    int h = tid >> 5, c = tid & 31;
    float s = bc[c];
    for (int d = 0; d < DIM; d++)
        s = fmaf(sh[h * 128 + d], Wc[c * 128 + d], s);
    outc[b * 64 + tid] = s;
}

// ---------------- pairwise distance + softmax over heads ----------------
__global__ void final_kernel(const float* __restrict__ c1, const float* __restrict__ c2,
                             float* __restrict__ out) {
    int b = threadIdx.x;
    if (b >= NGR) return;
    float dist[2];
    for (int h = 0; h < 2; h++) {
        float ss = 0.f;
        for (int c = 0; c < 32; c++) {
            float diff = c1[b * 64 + h * 32 + c] - c2[b * 64 + h * 32 + c] + 1e-6f;
            ss += diff * diff;
        }
        dist[h] = sqrtf(ss);
    }
    float mx = fmaxf(dist[0], dist[1]);
    float e0 = expf(dist[0] - mx), e1 = expf(dist[1] - mx);
    float inv = 1.f / (e0 + e1);
    out[b * 2 + 0] = e0 * inv;
    out[b * 2 + 1] = e1 * inv;
}

// ---------------- host launcher ----------------
extern "C" void kernel_launch(void* const* d_in, const int* in_sizes, int n_in,
                              void* d_out, int out_size) {
    const float* feat[2] = {(const float*)d_in[0], (const float*)d_in[1]};
    const int* srcs[2] = {(const int*)d_in[2], (const int*)d_in[6]};
    const int* dsts[2] = {(const int*)d_in[3], (const int*)d_in[7]};
    const int* ets[2]  = {(const int*)d_in[4], (const int*)d_in[8]};
    const int* gids[2] = {(const int*)d_in[5], (const int*)d_in[9]};
    const float* W_et   = (const float*)d_in[10];
    const float* b_et   = (const float*)d_in[11];
    const float* W_ih   = (const float*)d_in[12];
    const float* W_hh   = (const float*)d_in[13];
    const float* b_ih   = (const float*)d_in[14];
    const float* b_hh   = (const float*)d_in[15];
    const float* W_fc   = (const float*)d_in[16];
    const float* attn_l = (const float*)d_in[17];
    const float* attn_r = (const float*)d_in[18];
    const float* g_bias = (const float*)d_in[19];
    const float* W_cls  = (const float*)d_in[20];
    const float* b_cls  = (const float*)d_in[21];

    int N = in_sizes[0] / DIM;
    int E = in_sizes[2];

    float *h, *z, *gat, *el, *er, *hg, *cls, *cntf;
    int *deg, *off, *cur, *csrc, *cety;
    __half *a4, *a16, *h16, *gi16, *gh16, *bcat16, *wih16, *whh16, *wfc16;
    cudaGetSymbolAddress((void**)&h, g_h);
    cudaGetSymbolAddress((void**)&z, g_z);
    cudaGetSymbolAddress((void**)&gat, g_gat);
    cudaGetSymbolAddress((void**)&el, g_el);
    cudaGetSymbolAddress((void**)&er, g_er);
    cudaGetSymbolAddress((void**)&deg, g_deg);
    cudaGetSymbolAddress((void**)&off, g_off);
    cudaGetSymbolAddress((void**)&cur, g_cur);
    cudaGetSymbolAddress((void**)&csrc, g_csrc);
    cudaGetSymbolAddress((void**)&cety, g_cety);
    cudaGetSymbolAddress((void**)&hg, g_hg);
    cudaGetSymbolAddress((void**)&cls, g_cls);
    cudaGetSymbolAddress((void**)&cntf, g_cntf);
    cudaGetSymbolAddress((void**)&a4, g_a4);
    cudaGetSymbolAddress((void**)&a16, g_a16);
    cudaGetSymbolAddress((void**)&h16, g_h16);
    cudaGetSymbolAddress((void**)&gi16, g_gi16);
    cudaGetSymbolAddress((void**)&gh16, g_gh16);
    cudaGetSymbolAddress((void**)&bcat16, g_bcat16);
    cudaGetSymbolAddress((void**)&wih16, g_wih16);
    cudaGetSymbolAddress((void**)&whh16, g_whh16);
    cudaGetSymbolAddress((void**)&wfc16, g_wfc16);

    // convert weights (once per launch; tiny)
    bcat_kernel<<<(128 * 512 + 255) / 256, 256>>>(W_et, bcat16);
    cvt_kernel<<<(384 * 128 + 255) / 256, 256>>>(W_ih, wih16, 384 * 128);
    cvt_kernel<<<(384 * 128 + 255) / 256, 256>>>(W_hh, whh16, 384 * 128);
    cvt_kernel<<<(256 * 128 + 255) / 256, 256>>>(W_fc, wfc16, 256 * 128);

    int mblocks = (N + 127) / 128;

    for (int g = 0; g < 2; g++) {
        // CSR by dst
        zero_int_kernel<<<(N + 255) / 256, 256>>>(deg, N);
        hist_kernel<<<(E + 255) / 256, 256>>>(dsts[g], deg, E);
        scan_kernel<<<1, 1024>>>(deg, off, cur, N);
        scatter_kernel<<<(E + 255) / 256, 256>>>(srcs[g], dsts[g], ets[g], cur, csrc, cety, E);

        // initial features -> fp16
        cvt_kernel<<<(N * DIM + 255) / 256, 256>>>(feat[g], h16, N * DIM);

        const float* hcur = feat[g];
        for (int s = 0; s < NSTEPS; s++) {
            // per-etype aggregation of h -> A4 + counts
            agg4_kernel<<<N, DIM>>>(off, csrc, cety, h16, a4, cntf);
            // a = A4 @ Bcat^T + cnt-weighted b_et   (K=512, fp16 out)
            hgemm2<<<dim3(1, mblocks, 1), 256>>>(
                a4, bcat16, nullptr, nullptr, N, 128, 512,
                nullptr, nullptr, cntf, b_et, nullptr, a16, nullptr);
            // twin: gi = a @ W_ih^T + b_ih ; gh = h @ W_hh^T + b_hh  (fp16 out)
            hgemm2<<<dim3(3, mblocks, 2), 256>>>(
                a16, wih16, h16, whh16, N, 384, 128,
                b_ih, b_hh, nullptr, nullptr, nullptr, gi16, gh16);
            gru_kernel<<<(N * 64 + 255) / 256, 256>>>(
                (const __half2*)gi16, (const __half2*)gh16,
                (const float2*)hcur, (float2*)h, (__half2*)h16, N);
            hcur = h;
        }

        normsig_kernel<<<N, DIM>>>(h, h16);

        // GAT: z = h @ W_fc^T  (fp32 out)
        hgemm2<<<dim3(2, mblocks, 1), 256>>>(
            h16, wfc16, nullptr, nullptr, N, 256, 128,
            nullptr, nullptr, nullptr, nullptr, z, nullptr, nullptr);
        eler_kernel<<<N, 256>>>(z, attn_l, attn_r, el, er);
        gat_kernel<<<N, 256>>>(off, csrc, el, er, z, g_bias, gat);

        // pool + classify
        pool_kernel<<<NGR, 256>>>(gids[g], gat, hg, N);
        cls_kernel<<<NGR, 64>>>(hg, W_cls, b_cls, cls + g * NGR * 64);
    }

    final_kernel<<<1, 64>>>(cls, cls + NGR * 64, (float*)d_out);
}